// round 2
// baseline (speedup 1.0000x reference)
#include <cuda_runtime.h>
#include <math.h>

#define T_STEPS 512
#define BATCH   64
#define DIM     1024
#define HID     1024
#define N4      4096                 // 4 * HID
#define M_TOT   (T_STEPS * BATCH)    // 32768

// ---------------- scratch (static device globals; no runtime allocation) ----
__device__ float g_Xp[(size_t)M_TOT * N4];   // 512 MB: X @ Wx + b, [T*B, 4H]
__device__ float g_WhT[(size_t)N4 * HID];    // 16 MB: transposed hidden weights [4H][H]
__device__ float g_C[BATCH * HID];           // cell state

// ---------------- transpose Wh -> WhT[g*H + c][k] = Whg[k][c] ---------------
__global__ void transpose_wh_kernel(const float* __restrict__ W0,
                                    const float* __restrict__ W1,
                                    const float* __restrict__ W2,
                                    const float* __restrict__ W3) {
    __shared__ float tile[32][33];
    int g = blockIdx.z;
    const float* W = (g == 0) ? W0 : (g == 1) ? W1 : (g == 2) ? W2 : W3;
    int kbase = blockIdx.x * 32;
    int cbase = blockIdx.y * 32;
    int tx = threadIdx.x;
    for (int ty = threadIdx.y; ty < 32; ty += blockDim.y)
        tile[ty][tx] = W[(size_t)(kbase + ty) * HID + cbase + tx];
    __syncthreads();
    for (int ty = threadIdx.y; ty < 32; ty += blockDim.y)
        g_WhT[(size_t)(g * HID + cbase + ty) * HID + kbase + tx] = tile[tx][ty];
}

// ---------------- init cell state from C0 -----------------------------------
__global__ void init_c_kernel(const float* __restrict__ C0) {
    int i = blockIdx.x * 256 + threadIdx.x;
    if (i < BATCH * HID) g_C[i] = C0[i];
}

// ---------------- big GEMM: g_Xp = X @ [Wxi|Wxf|Wxo|Wxc] + bias -------------
// 128x128 tile, BK=8, 256 threads, 8x8 microtile.
__global__ __launch_bounds__(256)
void xproj_kernel(const float* __restrict__ X,
                  const float* __restrict__ W0, const float* __restrict__ W1,
                  const float* __restrict__ W2, const float* __restrict__ W3,
                  const float* __restrict__ b0, const float* __restrict__ b1,
                  const float* __restrict__ b2, const float* __restrict__ b3) {
    const int bn = blockIdx.x * 128;   // col base in [0,4096)
    const int bm = blockIdx.y * 128;   // row base in [0,32768)
    const int gate = bn >> 10;
    const float* W  = (gate == 0) ? W0 : (gate == 1) ? W1 : (gate == 2) ? W2 : W3;
    const float* bb = (gate == 0) ? b0 : (gate == 1) ? b1 : (gate == 2) ? b2 : b3;
    const int col0 = bn & (HID - 1);

    __shared__ float As[8][128];
    __shared__ float Bs[8][128];

    const int tid   = threadIdx.x;
    const int arow  = tid >> 1;            // 0..127
    const int acol4 = (tid & 1) * 4;       // 0 or 4
    const int brow  = tid >> 5;            // 0..7
    const int bcol4 = (tid & 31) * 4;      // 0..124
    const int tm    = (tid >> 4) * 8;      // 0..120
    const int tn    = (tid & 15) * 8;      // 0..120

    float acc[8][8];
    #pragma unroll
    for (int i = 0; i < 8; i++)
        #pragma unroll
        for (int j = 0; j < 8; j++) acc[i][j] = 0.0f;

    for (int k0 = 0; k0 < DIM; k0 += 8) {
        float4 av = *(const float4*)&X[(size_t)(bm + arow) * DIM + k0 + acol4];
        As[acol4 + 0][arow] = av.x;
        As[acol4 + 1][arow] = av.y;
        As[acol4 + 2][arow] = av.z;
        As[acol4 + 3][arow] = av.w;
        *(float4*)&Bs[brow][bcol4] =
            *(const float4*)&W[(size_t)(k0 + brow) * HID + col0 + bcol4];
        __syncthreads();
        #pragma unroll
        for (int kk = 0; kk < 8; kk++) {
            float4 a0 = *(const float4*)&As[kk][tm];
            float4 a1 = *(const float4*)&As[kk][tm + 4];
            float4 c0v = *(const float4*)&Bs[kk][tn];
            float4 c1v = *(const float4*)&Bs[kk][tn + 4];
            float ra[8] = {a0.x, a0.y, a0.z, a0.w, a1.x, a1.y, a1.z, a1.w};
            float rb[8] = {c0v.x, c0v.y, c0v.z, c0v.w, c1v.x, c1v.y, c1v.z, c1v.w};
            #pragma unroll
            for (int i = 0; i < 8; i++)
                #pragma unroll
                for (int j = 0; j < 8; j++)
                    acc[i][j] = fmaf(ra[i], rb[j], acc[i][j]);
        }
        __syncthreads();
    }

    #pragma unroll
    for (int i = 0; i < 8; i++) {
        size_t row = (size_t)(bm + tm + i);
        #pragma unroll
        for (int j = 0; j < 8; j += 4) {
            float4 v;
            v.x = acc[i][j + 0] + bb[col0 + tn + j + 0];
            v.y = acc[i][j + 1] + bb[col0 + tn + j + 1];
            v.z = acc[i][j + 2] + bb[col0 + tn + j + 2];
            v.w = acc[i][j + 3] + bb[col0 + tn + j + 3];
            *(float4*)&g_Xp[row * N4 + bn + tn + j] = v;
        }
    }
}

// ---------------- per-step recurrence: gates = Xp[t] + H @ Wh, update C/H ---
__device__ __forceinline__ void dot4(float& acc, const float4 h, const float4 v) {
    acc = fmaf(h.x, v.x, acc);
    acc = fmaf(h.y, v.y, acc);
    acc = fmaf(h.z, v.z, acc);
    acc = fmaf(h.w, v.w, acc);
}

// grid (32,4): 32 col-strips of 32, 4 row-strips of 16. 256 threads:
// tc = col within strip (32), tr (8) handles 2 adjacent rows, all 4 gates.
__global__ __launch_bounds__(256)
void lstm_step_kernel(const float* __restrict__ Hprev,
                      float* __restrict__ Hout, int t) {
    extern __shared__ float4 s_H[];   // [16 rows][256 float4] = 64 KB

    const int tid = threadIdx.x;
    const int tc  = tid & 31;
    const int tr  = tid >> 5;         // 0..7
    const int c0  = blockIdx.x * 32;
    const int r0  = blockIdx.y * 16;
    const int col = c0 + tc;

    // cooperative load of 16 H rows (rows are contiguous: r0*256 float4 base)
    const float4* Hp4 = (const float4*)Hprev;
    #pragma unroll
    for (int i = tid; i < 16 * 256; i += 256)
        s_H[i] = Hp4[(size_t)r0 * 256 + i];
    __syncthreads();

    const float4* Wi = (const float4*)(g_WhT + (size_t)(0 * HID + col) * HID);
    const float4* Wf = (const float4*)(g_WhT + (size_t)(1 * HID + col) * HID);
    const float4* Wo = (const float4*)(g_WhT + (size_t)(2 * HID + col) * HID);
    const float4* Wg = (const float4*)(g_WhT + (size_t)(3 * HID + col) * HID);
    const float4* h0p = s_H + (size_t)(tr * 2 + 0) * 256;
    const float4* h1p = s_H + (size_t)(tr * 2 + 1) * 256;

    float a0i = 0.f, a0f = 0.f, a0o = 0.f, a0g = 0.f;
    float a1i = 0.f, a1f = 0.f, a1o = 0.f, a1g = 0.f;

    #pragma unroll 4
    for (int k = 0; k < 256; k++) {
        float4 wi = Wi[k], wf = Wf[k], wo = Wo[k], wg = Wg[k];
        float4 h0 = h0p[k], h1 = h1p[k];
        dot4(a0i, h0, wi); dot4(a0f, h0, wf); dot4(a0o, h0, wo); dot4(a0g, h0, wg);
        dot4(a1i, h1, wi); dot4(a1f, h1, wf); dot4(a1o, h1, wo); dot4(a1g, h1, wg);
    }

    const float* Xp = g_Xp + (size_t)t * BATCH * N4;
    #pragma unroll
    for (int r = 0; r < 2; r++) {
        int row = r0 + tr * 2 + r;
        float gi = (r ? a1i : a0i) + Xp[(size_t)row * N4 + 0 * HID + col];
        float gf = (r ? a1f : a0f) + Xp[(size_t)row * N4 + 1 * HID + col];
        float go = (r ? a1o : a0o) + Xp[(size_t)row * N4 + 2 * HID + col];
        float gg = (r ? a1g : a0g) + Xp[(size_t)row * N4 + 3 * HID + col];

        float I = 1.0f / (1.0f + __expf(-gi));
        float F = 1.0f / (1.0f + __expf(-gf));
        float O = 1.0f / (1.0f + __expf(-go));
        float G = tanhf(gg);

        int idx = row * HID + col;
        float cn = fmaf(F, g_C[idx], I * G);
        g_C[idx] = cn;
        Hout[idx] = O * tanhf(cn);
    }
}

// ---------------- tail: H_f and C_f after outputs ---------------------------
__global__ void finalize_kernel(float* __restrict__ out) {
    int i = blockIdx.x * 256 + threadIdx.x;
    if (i < BATCH * HID) {
        size_t base = (size_t)T_STEPS * BATCH * HID;
        out[base + i] = out[(size_t)(T_STEPS - 1) * BATCH * HID + i];  // H_f
        out[base + BATCH * HID + i] = g_C[i];                          // C_f
    }
}

// ---------------- launch -----------------------------------------------------
extern "C" void kernel_launch(void* const* d_in, const int* in_sizes, int n_in,
                              void* d_out, int out_size) {
    const float* X   = (const float*)d_in[0];
    const float* H0  = (const float*)d_in[1];
    const float* C0  = (const float*)d_in[2];
    const float* Wxi = (const float*)d_in[3];
    const float* Wxf = (const float*)d_in[4];
    const float* Wxo = (const float*)d_in[5];
    const float* Wxc = (const float*)d_in[6];
    const float* Whi = (const float*)d_in[7];
    const float* Whf = (const float*)d_in[8];
    const float* Who = (const float*)d_in[9];
    const float* Whc = (const float*)d_in[10];
    const float* bi  = (const float*)d_in[11];
    const float* bf  = (const float*)d_in[12];
    const float* bo  = (const float*)d_in[13];
    const float* bc  = (const float*)d_in[14];
    float* out = (float*)d_out;

    cudaFuncSetAttribute(lstm_step_kernel,
                         cudaFuncAttributeMaxDynamicSharedMemorySize, 65536);

    transpose_wh_kernel<<<dim3(32, 32, 4), dim3(32, 8)>>>(Whi, Whf, Who, Whc);
    init_c_kernel<<<256, 256>>>(C0);
    xproj_kernel<<<dim3(32, 256), 256>>>(X, Wxi, Wxf, Wxo, Wxc, bi, bf, bo, bc);

    const float* Hprev = H0;
    for (int t = 0; t < T_STEPS; t++) {
        float* Hout = out + (size_t)t * BATCH * HID;
        lstm_step_kernel<<<dim3(32, 4), 256, 65536>>>(Hprev, Hout, t);
        Hprev = Hout;
    }
    finalize_kernel<<<256, 256>>>(out);
}

// round 5
// speedup vs baseline: 3.1616x; 3.1616x over previous
#include <cuda_runtime.h>
#include <math.h>

#define T_STEPS 512
#define BATCH   64
#define DIM     1024
#define HID     1024
#define N4      4096                 // 4 * HID
#define M_TOT   (T_STEPS * BATCH)    // 32768

// ---------------- scratch (static device globals; no runtime allocation) ----
__device__ float g_Xp[(size_t)M_TOT * N4];   // 512 MB: X @ Wx + b, [T*B, 4H]
__device__ float g_C[BATCH * HID];           // cell state

// ---------------- init cell state from C0 -----------------------------------
__global__ void init_c_kernel(const float* __restrict__ C0) {
    int i = blockIdx.x * 256 + threadIdx.x;
    if (i < BATCH * HID) g_C[i] = C0[i];
}

// ---------------- big GEMM: g_Xp = X @ [Wxi|Wxf|Wxo|Wxc] + bias -------------
// 128x128 tile, BK=8, 256 threads, 8x8 microtile.
__global__ __launch_bounds__(256)
void xproj_kernel(const float* __restrict__ X,
                  const float* __restrict__ W0, const float* __restrict__ W1,
                  const float* __restrict__ W2, const float* __restrict__ W3,
                  const float* __restrict__ b0, const float* __restrict__ b1,
                  const float* __restrict__ b2, const float* __restrict__ b3) {
    const int bn = blockIdx.x * 128;   // col base in [0,4096)
    const int bm = blockIdx.y * 128;   // row base in [0,32768)
    const int gate = bn >> 10;
    const float* W  = (gate == 0) ? W0 : (gate == 1) ? W1 : (gate == 2) ? W2 : W3;
    const float* bb = (gate == 0) ? b0 : (gate == 1) ? b1 : (gate == 2) ? b2 : b3;
    const int col0 = bn & (HID - 1);

    __shared__ float As[8][128];
    __shared__ float Bs[8][128];

    const int tid   = threadIdx.x;
    const int arow  = tid >> 1;            // 0..127
    const int acol4 = (tid & 1) * 4;       // 0 or 4
    const int brow  = tid >> 5;            // 0..7
    const int bcol4 = (tid & 31) * 4;      // 0..124
    const int tm    = (tid >> 4) * 8;      // 0..120
    const int tn    = (tid & 15) * 8;      // 0..120

    float acc[8][8];
    #pragma unroll
    for (int i = 0; i < 8; i++)
        #pragma unroll
        for (int j = 0; j < 8; j++) acc[i][j] = 0.0f;

    for (int k0 = 0; k0 < DIM; k0 += 8) {
        float4 av = *(const float4*)&X[(size_t)(bm + arow) * DIM + k0 + acol4];
        As[acol4 + 0][arow] = av.x;
        As[acol4 + 1][arow] = av.y;
        As[acol4 + 2][arow] = av.z;
        As[acol4 + 3][arow] = av.w;
        *(float4*)&Bs[brow][bcol4] =
            *(const float4*)&W[(size_t)(k0 + brow) * HID + col0 + bcol4];
        __syncthreads();
        #pragma unroll
        for (int kk = 0; kk < 8; kk++) {
            float4 a0 = *(const float4*)&As[kk][tm];
            float4 a1 = *(const float4*)&As[kk][tm + 4];
            float4 c0v = *(const float4*)&Bs[kk][tn];
            float4 c1v = *(const float4*)&Bs[kk][tn + 4];
            float ra[8] = {a0.x, a0.y, a0.z, a0.w, a1.x, a1.y, a1.z, a1.w};
            float rb[8] = {c0v.x, c0v.y, c0v.z, c0v.w, c1v.x, c1v.y, c1v.z, c1v.w};
            #pragma unroll
            for (int i = 0; i < 8; i++)
                #pragma unroll
                for (int j = 0; j < 8; j++)
                    acc[i][j] = fmaf(ra[i], rb[j], acc[i][j]);
        }
        __syncthreads();
    }

    #pragma unroll
    for (int i = 0; i < 8; i++) {
        size_t row = (size_t)(bm + tm + i);
        #pragma unroll
        for (int j = 0; j < 8; j += 4) {
            float4 v;
            v.x = acc[i][j + 0] + bb[col0 + tn + j + 0];
            v.y = acc[i][j + 1] + bb[col0 + tn + j + 1];
            v.z = acc[i][j + 2] + bb[col0 + tn + j + 2];
            v.w = acc[i][j + 3] + bb[col0 + tn + j + 3];
            *(float4*)&g_Xp[row * N4 + bn + tn + j] = v;
        }
    }
}

// ---------------- fused per-step: gates = Xp[t] + H @ Wh, update C/H --------
// grid (32, 4): 32 hidden-col strips x 4 row strips of 16. Each block computes
// a 16-row x 32-col tile for ALL 4 gates (K=1024), then applies the LSTM cell
// epilogue in-block. 256 threads.
__global__ __launch_bounds__(256)
void lstm_step_fused(const float* __restrict__ Hprev,
                     const float* __restrict__ W0, const float* __restrict__ W1,
                     const float* __restrict__ W2, const float* __restrict__ W3,
                     int t,
                     float* __restrict__ Hout) {
    __shared__ float As[2][32][20];    // [buf][k][row(16) pad 20] 16B-row-aligned
    __shared__ float Bs[2][32][128];   // [buf][k][gate*32 + col]
    __shared__ float sg[4][16][32];    // gate results for epilogue

    const int tid = threadIdx.x;
    const int colbase = blockIdx.x * 32;   // hidden column base
    const int r0 = blockIdx.y * 16;        // batch row base

    // device-side pointer into the precomputed input projection (device symbol!)
    const float* Xp_t = g_Xp + (size_t)t * BATCH * N4;

    const float* Ws[4] = {W0, W1, W2, W3};

    // load mapping: one warp loads one row of 32 consecutive floats
    const int lk = tid & 31;
    const int lw = tid >> 5;               // 0..7

    // compute mapping
    const int cg   = tid & 63;
    const int rg   = tid >> 6;             // 0..3
    const int gate = cg >> 4;
    const int cp   = cg & 15;

    float acc[4][2];
    #pragma unroll
    for (int i = 0; i < 4; i++) { acc[i][0] = 0.f; acc[i][1] = 0.f; }

    // --- preload k-tile 0 ---
    #pragma unroll
    for (int j = 0; j < 2; j++)
        As[0][lk][lw + j * 8] = Hprev[(size_t)(r0 + lw + j * 8) * HID + lk];
    #pragma unroll
    for (int g = 0; g < 4; g++)
        #pragma unroll
        for (int i = 0; i < 4; i++)
            Bs[0][lw + i * 8][g * 32 + lk] =
                Ws[g][(size_t)(lw + i * 8) * HID + colbase + lk];
    __syncthreads();

    int buf = 0;
    for (int kt = 0; kt < HID / 32; kt++) {
        float a_regs[2];
        float b_regs[4][4];
        const int k0n = (kt + 1) * 32;
        if (kt + 1 < HID / 32) {
            #pragma unroll
            for (int j = 0; j < 2; j++)
                a_regs[j] = Hprev[(size_t)(r0 + lw + j * 8) * HID + k0n + lk];
            #pragma unroll
            for (int g = 0; g < 4; g++)
                #pragma unroll
                for (int i = 0; i < 4; i++)
                    b_regs[g][i] =
                        Ws[g][(size_t)(k0n + lw + i * 8) * HID + colbase + lk];
        }

        #pragma unroll
        for (int kk = 0; kk < 32; kk++) {
            float4 a = *(const float4*)&As[buf][kk][rg * 4];
            float2 b = *(const float2*)&Bs[buf][kk][gate * 32 + cp * 2];
            acc[0][0] = fmaf(a.x, b.x, acc[0][0]);
            acc[0][1] = fmaf(a.x, b.y, acc[0][1]);
            acc[1][0] = fmaf(a.y, b.x, acc[1][0]);
            acc[1][1] = fmaf(a.y, b.y, acc[1][1]);
            acc[2][0] = fmaf(a.z, b.x, acc[2][0]);
            acc[2][1] = fmaf(a.z, b.y, acc[2][1]);
            acc[3][0] = fmaf(a.w, b.x, acc[3][0]);
            acc[3][1] = fmaf(a.w, b.y, acc[3][1]);
        }

        if (kt + 1 < HID / 32) {
            const int nb = buf ^ 1;
            #pragma unroll
            for (int j = 0; j < 2; j++)
                As[nb][lk][lw + j * 8] = a_regs[j];
            #pragma unroll
            for (int g = 0; g < 4; g++)
                #pragma unroll
                for (int i = 0; i < 4; i++)
                    Bs[nb][lw + i * 8][g * 32 + lk] = b_regs[g][i];
            __syncthreads();
            buf = nb;
        }
    }

    // --- stash gate partials for the epilogue ---
    #pragma unroll
    for (int i = 0; i < 4; i++) {
        sg[gate][rg * 4 + i][cp * 2 + 0] = acc[i][0];
        sg[gate][rg * 4 + i][cp * 2 + 1] = acc[i][1];
    }
    __syncthreads();

    // --- fused LSTM cell epilogue: 512 cells, 2 per thread ---
    #pragma unroll
    for (int e = tid; e < 512; e += 256) {
        const int row = e >> 5;            // 0..15
        const int col = e & 31;            // 0..31
        const size_t xb = (size_t)(r0 + row) * N4 + colbase + col;

        float gi = sg[0][row][col] + Xp_t[xb + 0 * HID];
        float gf = sg[1][row][col] + Xp_t[xb + 1 * HID];
        float go = sg[2][row][col] + Xp_t[xb + 2 * HID];
        float gg = sg[3][row][col] + Xp_t[xb + 3 * HID];

        float I = 1.0f / (1.0f + __expf(-gi));
        float F = 1.0f / (1.0f + __expf(-gf));
        float O = 1.0f / (1.0f + __expf(-go));
        float G = tanhf(gg);

        const int idx = (r0 + row) * HID + colbase + col;
        float cn = fmaf(F, g_C[idx], I * G);
        g_C[idx] = cn;
        Hout[idx] = O * tanhf(cn);
    }
}

// ---------------- tail: H_f and C_f after outputs ---------------------------
__global__ void finalize_kernel(float* __restrict__ out) {
    int i = blockIdx.x * 256 + threadIdx.x;
    if (i < BATCH * HID) {
        size_t base = (size_t)T_STEPS * BATCH * HID;
        out[base + i] = out[(size_t)(T_STEPS - 1) * BATCH * HID + i];  // H_f
        out[base + BATCH * HID + i] = g_C[i];                          // C_f
    }
}

// ---------------- launch -----------------------------------------------------
extern "C" void kernel_launch(void* const* d_in, const int* in_sizes, int n_in,
                              void* d_out, int out_size) {
    const float* X   = (const float*)d_in[0];
    const float* H0  = (const float*)d_in[1];
    const float* C0  = (const float*)d_in[2];
    const float* Wxi = (const float*)d_in[3];
    const float* Wxf = (const float*)d_in[4];
    const float* Wxo = (const float*)d_in[5];
    const float* Wxc = (const float*)d_in[6];
    const float* Whi = (const float*)d_in[7];
    const float* Whf = (const float*)d_in[8];
    const float* Who = (const float*)d_in[9];
    const float* Whc = (const float*)d_in[10];
    const float* bi  = (const float*)d_in[11];
    const float* bf  = (const float*)d_in[12];
    const float* bo  = (const float*)d_in[13];
    const float* bc  = (const float*)d_in[14];
    float* out = (float*)d_out;

    init_c_kernel<<<256, 256>>>(C0);
    xproj_kernel<<<dim3(32, 256), 256>>>(X, Wxi, Wxf, Wxo, Wxc, bi, bf, bo, bc);

    const float* Hprev = H0;
    for (int t = 0; t < T_STEPS; t++) {
        float* Hout = out + (size_t)t * BATCH * HID;
        lstm_step_fused<<<dim3(32, 4), 256>>>(Hprev, Whi, Whf, Who, Whc, t, Hout);
        Hprev = Hout;
    }
    finalize_kernel<<<256, 256>>>(out);
}

// round 6
// speedup vs baseline: 3.5873x; 1.1347x over previous
#include <cuda_runtime.h>
#include <math.h>
#include <stdint.h>

#define T_STEPS 512
#define BATCH   64
#define DIM     1024
#define HID     1024
#define N4      4096                 // 4 * HID
#define M_TOT   (T_STEPS * BATCH)    // 32768

// ---------------- scratch (static device globals; no runtime allocation) ----
__device__ float g_Xp[(size_t)M_TOT * N4];   // 512 MB: X @ Wx + b, [T*B, 4H]
__device__ float g_C[BATCH * HID];           // cell state

// ---------------- init cell state from C0 -----------------------------------
__global__ void init_c_kernel(const float* __restrict__ C0) {
    int i = blockIdx.x * 256 + threadIdx.x;
    if (i < BATCH * HID) g_C[i] = C0[i];
}

// ---------------- tf32 helpers ----------------------------------------------
__device__ __forceinline__ uint32_t cvt_tf32(float x) {
    uint32_t r;
    asm("cvt.rna.tf32.f32 %0, %1;" : "=r"(r) : "f"(x));
    return r;
}

__device__ __forceinline__ void mma_tf32(float& c0, float& c1, float& c2, float& c3,
                                         uint32_t a0, uint32_t a1, uint32_t a2, uint32_t a3,
                                         uint32_t b0, uint32_t b1) {
    asm volatile(
        "mma.sync.aligned.m16n8k8.row.col.f32.tf32.tf32.f32 "
        "{%0,%1,%2,%3}, {%4,%5,%6,%7}, {%8,%9}, {%0,%1,%2,%3};\n"
        : "+f"(c0), "+f"(c1), "+f"(c2), "+f"(c3)
        : "r"(a0), "r"(a1), "r"(a2), "r"(a3), "r"(b0), "r"(b1));
}

// ---------------- big GEMM (tf32 tensor cores): g_Xp = X @ Wx + b ------------
// 128x128 output tile per block, BK=16, 256 threads = 8 warps (2x4 warp grid),
// each warp 64x32 via 4x4 m16n8k8 fragments. Double-buffered smem holding
// tf32-converted operands.
__global__ __launch_bounds__(256)
void xproj_tf32_kernel(const float* __restrict__ X,
                       const float* __restrict__ W0, const float* __restrict__ W1,
                       const float* __restrict__ W2, const float* __restrict__ W3,
                       const float* __restrict__ b0, const float* __restrict__ b1,
                       const float* __restrict__ b2, const float* __restrict__ b3) {
    const int bn = blockIdx.x * 128;   // col base in [0,4096)
    const int bm = blockIdx.y * 128;   // row base in [0,32768)
    const int gate = bn >> 10;
    const float* W  = (gate == 0) ? W0 : (gate == 1) ? W1 : (gate == 2) ? W2 : W3;
    const float* bb = (gate == 0) ? b0 : (gate == 1) ? b1 : (gate == 2) ? b2 : b3;
    const int col0 = bn & (HID - 1);

    __shared__ uint32_t As[2][16][132];   // [buf][k][m]  (pad 132 vs 128)
    __shared__ uint32_t Bs[2][16][128];   // [buf][k][n]

    const int tid  = threadIdx.x;
    const int lane = tid & 31;
    const int warp = tid >> 5;
    const int wm   = warp >> 2;          // 0..1 -> m offset wm*64
    const int wn   = warp & 3;           // 0..3 -> n offset wn*32
    const int qg   = lane >> 2;          // fragment row group 0..7
    const int qk   = lane & 3;           // fragment k/col slot 0..3

    // load mapping
    const int ar = tid >> 1;             // A row 0..127
    const int ac = (tid & 1) * 8;        // A k base 0 or 8
    const int br = tid >> 4;             // B k row 0..15
    const int bc = (tid & 15) * 8;       // B col base 0..120

    float c[4][4][4];
    #pragma unroll
    for (int mt = 0; mt < 4; mt++)
        #pragma unroll
        for (int nt = 0; nt < 4; nt++)
            #pragma unroll
            for (int r = 0; r < 4; r++) c[mt][nt][r] = 0.0f;

    // ---- preload k-tile 0 ----
    {
        float4 av0 = *(const float4*)&X[(size_t)(bm + ar) * DIM + ac];
        float4 av1 = *(const float4*)&X[(size_t)(bm + ar) * DIM + ac + 4];
        float4 bv0 = *(const float4*)&W[(size_t)br * HID + col0 + bc];
        float4 bv1 = *(const float4*)&W[(size_t)br * HID + col0 + bc + 4];
        As[0][ac + 0][ar] = cvt_tf32(av0.x); As[0][ac + 1][ar] = cvt_tf32(av0.y);
        As[0][ac + 2][ar] = cvt_tf32(av0.z); As[0][ac + 3][ar] = cvt_tf32(av0.w);
        As[0][ac + 4][ar] = cvt_tf32(av1.x); As[0][ac + 5][ar] = cvt_tf32(av1.y);
        As[0][ac + 6][ar] = cvt_tf32(av1.z); As[0][ac + 7][ar] = cvt_tf32(av1.w);
        Bs[0][br][bc + 0] = cvt_tf32(bv0.x); Bs[0][br][bc + 1] = cvt_tf32(bv0.y);
        Bs[0][br][bc + 2] = cvt_tf32(bv0.z); Bs[0][br][bc + 3] = cvt_tf32(bv0.w);
        Bs[0][br][bc + 4] = cvt_tf32(bv1.x); Bs[0][br][bc + 5] = cvt_tf32(bv1.y);
        Bs[0][br][bc + 6] = cvt_tf32(bv1.z); Bs[0][br][bc + 7] = cvt_tf32(bv1.w);
    }
    __syncthreads();

    int buf = 0;
    for (int kt = 0; kt < DIM / 16; kt++) {
        float4 av0, av1, bv0, bv1;
        const int k0n = (kt + 1) * 16;
        const bool has_next = (kt + 1 < DIM / 16);
        if (has_next) {
            av0 = *(const float4*)&X[(size_t)(bm + ar) * DIM + k0n + ac];
            av1 = *(const float4*)&X[(size_t)(bm + ar) * DIM + k0n + ac + 4];
            bv0 = *(const float4*)&W[(size_t)(k0n + br) * HID + col0 + bc];
            bv1 = *(const float4*)&W[(size_t)(k0n + br) * HID + col0 + bc + 4];
        }

        // ---- compute on current buffer: two k8 steps ----
        #pragma unroll
        for (int k8 = 0; k8 < 16; k8 += 8) {
            uint32_t af[4][4];
            #pragma unroll
            for (int mt = 0; mt < 4; mt++) {
                const int m = wm * 64 + mt * 16 + qg;
                af[mt][0] = As[buf][k8 + qk][m];
                af[mt][1] = As[buf][k8 + qk][m + 8];
                af[mt][2] = As[buf][k8 + 4 + qk][m];
                af[mt][3] = As[buf][k8 + 4 + qk][m + 8];
            }
            uint32_t bf[4][2];
            #pragma unroll
            for (int nt = 0; nt < 4; nt++) {
                const int n = wn * 32 + nt * 8 + qg;
                bf[nt][0] = Bs[buf][k8 + qk][n];
                bf[nt][1] = Bs[buf][k8 + 4 + qk][n];
            }
            #pragma unroll
            for (int mt = 0; mt < 4; mt++)
                #pragma unroll
                for (int nt = 0; nt < 4; nt++)
                    mma_tf32(c[mt][nt][0], c[mt][nt][1], c[mt][nt][2], c[mt][nt][3],
                             af[mt][0], af[mt][1], af[mt][2], af[mt][3],
                             bf[nt][0], bf[nt][1]);
        }

        if (has_next) {
            const int nb = buf ^ 1;
            As[nb][ac + 0][ar] = cvt_tf32(av0.x); As[nb][ac + 1][ar] = cvt_tf32(av0.y);
            As[nb][ac + 2][ar] = cvt_tf32(av0.z); As[nb][ac + 3][ar] = cvt_tf32(av0.w);
            As[nb][ac + 4][ar] = cvt_tf32(av1.x); As[nb][ac + 5][ar] = cvt_tf32(av1.y);
            As[nb][ac + 6][ar] = cvt_tf32(av1.z); As[nb][ac + 7][ar] = cvt_tf32(av1.w);
            Bs[nb][br][bc + 0] = cvt_tf32(bv0.x); Bs[nb][br][bc + 1] = cvt_tf32(bv0.y);
            Bs[nb][br][bc + 2] = cvt_tf32(bv0.z); Bs[nb][br][bc + 3] = cvt_tf32(bv0.w);
            Bs[nb][br][bc + 4] = cvt_tf32(bv1.x); Bs[nb][br][bc + 5] = cvt_tf32(bv1.y);
            Bs[nb][br][bc + 6] = cvt_tf32(bv1.z); Bs[nb][br][bc + 7] = cvt_tf32(bv1.w);
            __syncthreads();
            buf = nb;
        }
    }

    // ---- epilogue: add bias, store to g_Xp ----
    #pragma unroll
    for (int mt = 0; mt < 4; mt++) {
        #pragma unroll
        for (int nt = 0; nt < 4; nt++) {
            const int colg = wn * 32 + nt * 8 + 2 * qk;       // within 128 tile
            const float bx0 = bb[col0 + colg];
            const float bx1 = bb[col0 + colg + 1];
            const size_t row0 = (size_t)(bm + wm * 64 + mt * 16 + qg);
            float2 v0 = make_float2(c[mt][nt][0] + bx0, c[mt][nt][1] + bx1);
            float2 v1 = make_float2(c[mt][nt][2] + bx0, c[mt][nt][3] + bx1);
            *(float2*)&g_Xp[row0 * N4 + bn + colg]       = v0;
            *(float2*)&g_Xp[(row0 + 8) * N4 + bn + colg] = v1;
        }
    }
}

// ---------------- fused per-step: gates = Xp[t] + H @ Wh, update C/H --------
// grid (32, 4): 32 hidden-col strips x 4 row strips of 16. Each block computes
// a 16-row x 32-col tile for ALL 4 gates (K=1024), then applies the LSTM cell
// epilogue in-block. 256 threads.
__global__ __launch_bounds__(256)
void lstm_step_fused(const float* __restrict__ Hprev,
                     const float* __restrict__ W0, const float* __restrict__ W1,
                     const float* __restrict__ W2, const float* __restrict__ W3,
                     int t,
                     float* __restrict__ Hout) {
    __shared__ float As[2][32][20];    // [buf][k][row(16) pad 20] 16B-row-aligned
    __shared__ float Bs[2][32][128];   // [buf][k][gate*32 + col]
    __shared__ float sg[4][16][32];    // gate results for epilogue

    const int tid = threadIdx.x;
    const int colbase = blockIdx.x * 32;   // hidden column base
    const int r0 = blockIdx.y * 16;        // batch row base

    // device-side pointer into the precomputed input projection
    const float* Xp_t = g_Xp + (size_t)t * BATCH * N4;

    const float* Ws[4] = {W0, W1, W2, W3};

    // load mapping: one warp loads one row of 32 consecutive floats
    const int lk = tid & 31;
    const int lw = tid >> 5;               // 0..7

    // compute mapping
    const int cg   = tid & 63;
    const int rg   = tid >> 6;             // 0..3
    const int gate = cg >> 4;
    const int cp   = cg & 15;

    float acc[4][2];
    #pragma unroll
    for (int i = 0; i < 4; i++) { acc[i][0] = 0.f; acc[i][1] = 0.f; }

    // --- preload k-tile 0 ---
    #pragma unroll
    for (int j = 0; j < 2; j++)
        As[0][lk][lw + j * 8] = Hprev[(size_t)(r0 + lw + j * 8) * HID + lk];
    #pragma unroll
    for (int g = 0; g < 4; g++)
        #pragma unroll
        for (int i = 0; i < 4; i++)
            Bs[0][lw + i * 8][g * 32 + lk] =
                Ws[g][(size_t)(lw + i * 8) * HID + colbase + lk];
    __syncthreads();

    int buf = 0;
    for (int kt = 0; kt < HID / 32; kt++) {
        float a_regs[2];
        float b_regs[4][4];
        const int k0n = (kt + 1) * 32;
        if (kt + 1 < HID / 32) {
            #pragma unroll
            for (int j = 0; j < 2; j++)
                a_regs[j] = Hprev[(size_t)(r0 + lw + j * 8) * HID + k0n + lk];
            #pragma unroll
            for (int g = 0; g < 4; g++)
                #pragma unroll
                for (int i = 0; i < 4; i++)
                    b_regs[g][i] =
                        Ws[g][(size_t)(k0n + lw + i * 8) * HID + colbase + lk];
        }

        #pragma unroll
        for (int kk = 0; kk < 32; kk++) {
            float4 a = *(const float4*)&As[buf][kk][rg * 4];
            float2 b = *(const float2*)&Bs[buf][kk][gate * 32 + cp * 2];
            acc[0][0] = fmaf(a.x, b.x, acc[0][0]);
            acc[0][1] = fmaf(a.x, b.y, acc[0][1]);
            acc[1][0] = fmaf(a.y, b.x, acc[1][0]);
            acc[1][1] = fmaf(a.y, b.y, acc[1][1]);
            acc[2][0] = fmaf(a.z, b.x, acc[2][0]);
            acc[2][1] = fmaf(a.z, b.y, acc[2][1]);
            acc[3][0] = fmaf(a.w, b.x, acc[3][0]);
            acc[3][1] = fmaf(a.w, b.y, acc[3][1]);
        }

        if (kt + 1 < HID / 32) {
            const int nb = buf ^ 1;
            #pragma unroll
            for (int j = 0; j < 2; j++)
                As[nb][lk][lw + j * 8] = a_regs[j];
            #pragma unroll
            for (int g = 0; g < 4; g++)
                #pragma unroll
                for (int i = 0; i < 4; i++)
                    Bs[nb][lw + i * 8][g * 32 + lk] = b_regs[g][i];
            __syncthreads();
            buf = nb;
        }
    }

    // --- stash gate partials for the epilogue ---
    #pragma unroll
    for (int i = 0; i < 4; i++) {
        sg[gate][rg * 4 + i][cp * 2 + 0] = acc[i][0];
        sg[gate][rg * 4 + i][cp * 2 + 1] = acc[i][1];
    }
    __syncthreads();

    // --- fused LSTM cell epilogue: 512 cells, 2 per thread ---
    #pragma unroll
    for (int e = tid; e < 512; e += 256) {
        const int row = e >> 5;            // 0..15
        const int col = e & 31;            // 0..31
        const size_t xb = (size_t)(r0 + row) * N4 + colbase + col;

        float gi = sg[0][row][col] + Xp_t[xb + 0 * HID];
        float gf = sg[1][row][col] + Xp_t[xb + 1 * HID];
        float go = sg[2][row][col] + Xp_t[xb + 2 * HID];
        float gg = sg[3][row][col] + Xp_t[xb + 3 * HID];

        float I = 1.0f / (1.0f + __expf(-gi));
        float F = 1.0f / (1.0f + __expf(-gf));
        float O = 1.0f / (1.0f + __expf(-go));
        float G = tanhf(gg);

        const int idx = (r0 + row) * HID + colbase + col;
        float cn = fmaf(F, g_C[idx], I * G);
        g_C[idx] = cn;
        Hout[idx] = O * tanhf(cn);
    }
}

// ---------------- tail: H_f and C_f after outputs ---------------------------
__global__ void finalize_kernel(float* __restrict__ out) {
    int i = blockIdx.x * 256 + threadIdx.x;
    if (i < BATCH * HID) {
        size_t base = (size_t)T_STEPS * BATCH * HID;
        out[base + i] = out[(size_t)(T_STEPS - 1) * BATCH * HID + i];  // H_f
        out[base + BATCH * HID + i] = g_C[i];                          // C_f
    }
}

// ---------------- launch -----------------------------------------------------
extern "C" void kernel_launch(void* const* d_in, const int* in_sizes, int n_in,
                              void* d_out, int out_size) {
    const float* X   = (const float*)d_in[0];
    const float* H0  = (const float*)d_in[1];
    const float* C0  = (const float*)d_in[2];
    const float* Wxi = (const float*)d_in[3];
    const float* Wxf = (const float*)d_in[4];
    const float* Wxo = (const float*)d_in[5];
    const float* Wxc = (const float*)d_in[6];
    const float* Whi = (const float*)d_in[7];
    const float* Whf = (const float*)d_in[8];
    const float* Who = (const float*)d_in[9];
    const float* Whc = (const float*)d_in[10];
    const float* bi  = (const float*)d_in[11];
    const float* bf  = (const float*)d_in[12];
    const float* bo  = (const float*)d_in[13];
    const float* bc  = (const float*)d_in[14];
    float* out = (float*)d_out;

    init_c_kernel<<<256, 256>>>(C0);
    xproj_tf32_kernel<<<dim3(32, 256), 256>>>(X, Wxi, Wxf, Wxo, Wxc,
                                              bi, bf, bo, bc);

    const float* Hprev = H0;
    for (int t = 0; t < T_STEPS; t++) {
        float* Hout = out + (size_t)t * BATCH * HID;
        lstm_step_fused<<<dim3(32, 4), 256>>>(Hprev, Whi, Whf, Who, Whc, t, Hout);
        Hprev = Hout;
    }
    finalize_kernel<<<256, 256>>>(out);
}

// round 7
// speedup vs baseline: 5.4211x; 1.5112x over previous
#include <cuda_runtime.h>
#include <math.h>
#include <stdint.h>

#define T_STEPS 512
#define BATCH   64
#define DIM     1024
#define HID     1024
#define N4      4096                 // 4 * HID
#define M_TOT   (T_STEPS * BATCH)    // 32768

// ---------------- scratch (static device globals; no runtime allocation) ----
__device__ float g_Xp[(size_t)M_TOT * N4];   // 512 MB: X @ Wx + b, [T*B, 4H]
__device__ float g_C[BATCH * HID];           // cell state

// ---------------- init cell state from C0 -----------------------------------
__global__ void init_c_kernel(const float* __restrict__ C0) {
    int i = blockIdx.x * 256 + threadIdx.x;
    if (i < BATCH * HID) g_C[i] = C0[i];
}

// ---------------- tf32 helpers ----------------------------------------------
__device__ __forceinline__ uint32_t cvt_tf32(float x) {
    uint32_t r;
    asm("cvt.rna.tf32.f32 %0, %1;" : "=r"(r) : "f"(x));
    return r;
}

__device__ __forceinline__ void mma_tf32(float& c0, float& c1, float& c2, float& c3,
                                         uint32_t a0, uint32_t a1, uint32_t a2, uint32_t a3,
                                         uint32_t b0, uint32_t b1) {
    asm volatile(
        "mma.sync.aligned.m16n8k8.row.col.f32.tf32.tf32.f32 "
        "{%0,%1,%2,%3}, {%4,%5,%6,%7}, {%8,%9}, {%0,%1,%2,%3};\n"
        : "+f"(c0), "+f"(c1), "+f"(c2), "+f"(c3)
        : "r"(a0), "r"(a1), "r"(a2), "r"(a3), "r"(b0), "r"(b1));
}

// ---------------- big GEMM (tf32 tensor cores): g_Xp = X @ Wx + b ------------
// 128x128 output tile per block, BK=16, 256 threads = 8 warps (2x4 warp grid),
// each warp 64x32 via 4x4 m16n8k8 fragments. Pads chosen = 136 (== 8 mod 32)
// so fragment LDS banks are (8*qk + qg) -> conflict-free.
__global__ __launch_bounds__(256)
void xproj_tf32_kernel(const float* __restrict__ X,
                       const float* __restrict__ W0, const float* __restrict__ W1,
                       const float* __restrict__ W2, const float* __restrict__ W3,
                       const float* __restrict__ b0, const float* __restrict__ b1,
                       const float* __restrict__ b2, const float* __restrict__ b3) {
    const int bn = blockIdx.x * 128;   // col base in [0,4096)
    const int bm = blockIdx.y * 128;   // row base in [0,32768)
    const int gate = bn >> 10;
    const float* W  = (gate == 0) ? W0 : (gate == 1) ? W1 : (gate == 2) ? W2 : W3;
    const float* bb = (gate == 0) ? b0 : (gate == 1) ? b1 : (gate == 2) ? b2 : b3;
    const int col0 = bn & (HID - 1);

    __shared__ uint32_t As[2][16][136];
    __shared__ uint32_t Bs[2][16][136];

    const int tid  = threadIdx.x;
    const int lane = tid & 31;
    const int warp = tid >> 5;
    const int wm   = warp >> 2;          // 0..1 -> m offset wm*64
    const int wn   = warp & 3;           // 0..3 -> n offset wn*32
    const int qg   = lane >> 2;          // fragment row group 0..7
    const int qk   = lane & 3;           // fragment k/col slot 0..3

    // load mapping
    const int ar  = tid >> 1;            // A row 0..127
    const int ac  = (tid & 1) * 8;       // A k base 0 or 8
    const int br  = tid >> 4;            // B k row 0..15
    const int bcn = tid & 15;            // B col low index, cols bcn + 16j

    float c[4][4][4];
    #pragma unroll
    for (int mt = 0; mt < 4; mt++)
        #pragma unroll
        for (int nt = 0; nt < 4; nt++)
            #pragma unroll
            for (int r = 0; r < 4; r++) c[mt][nt][r] = 0.0f;

    // ---- preload k-tile 0 ----
    {
        float4 av0 = *(const float4*)&X[(size_t)(bm + ar) * DIM + ac];
        float4 av1 = *(const float4*)&X[(size_t)(bm + ar) * DIM + ac + 4];
        As[0][ac + 0][ar] = cvt_tf32(av0.x); As[0][ac + 1][ar] = cvt_tf32(av0.y);
        As[0][ac + 2][ar] = cvt_tf32(av0.z); As[0][ac + 3][ar] = cvt_tf32(av0.w);
        As[0][ac + 4][ar] = cvt_tf32(av1.x); As[0][ac + 5][ar] = cvt_tf32(av1.y);
        As[0][ac + 6][ar] = cvt_tf32(av1.z); As[0][ac + 7][ar] = cvt_tf32(av1.w);
        #pragma unroll
        for (int j = 0; j < 8; j++)
            Bs[0][br][bcn + 16 * j] =
                cvt_tf32(W[(size_t)br * HID + col0 + bcn + 16 * j]);
    }
    __syncthreads();

    int buf = 0;
    for (int kt = 0; kt < DIM / 16; kt++) {
        float4 av0, av1;
        float bvr[8];
        const int k0n = (kt + 1) * 16;
        const bool has_next = (kt + 1 < DIM / 16);
        if (has_next) {
            av0 = *(const float4*)&X[(size_t)(bm + ar) * DIM + k0n + ac];
            av1 = *(const float4*)&X[(size_t)(bm + ar) * DIM + k0n + ac + 4];
            #pragma unroll
            for (int j = 0; j < 8; j++)
                bvr[j] = W[(size_t)(k0n + br) * HID + col0 + bcn + 16 * j];
        }

        // ---- compute on current buffer: two k8 steps ----
        #pragma unroll
        for (int k8 = 0; k8 < 16; k8 += 8) {
            uint32_t af[4][4];
            #pragma unroll
            for (int mt = 0; mt < 4; mt++) {
                const int m = wm * 64 + mt * 16 + qg;
                af[mt][0] = As[buf][k8 + qk][m];
                af[mt][1] = As[buf][k8 + qk][m + 8];
                af[mt][2] = As[buf][k8 + 4 + qk][m];
                af[mt][3] = As[buf][k8 + 4 + qk][m + 8];
            }
            uint32_t bf[4][2];
            #pragma unroll
            for (int nt = 0; nt < 4; nt++) {
                const int n = wn * 32 + nt * 8 + qg;
                bf[nt][0] = Bs[buf][k8 + qk][n];
                bf[nt][1] = Bs[buf][k8 + 4 + qk][n];
            }
            #pragma unroll
            for (int mt = 0; mt < 4; mt++)
                #pragma unroll
                for (int nt = 0; nt < 4; nt++)
                    mma_tf32(c[mt][nt][0], c[mt][nt][1], c[mt][nt][2], c[mt][nt][3],
                             af[mt][0], af[mt][1], af[mt][2], af[mt][3],
                             bf[nt][0], bf[nt][1]);
        }

        if (has_next) {
            const int nb = buf ^ 1;
            As[nb][ac + 0][ar] = cvt_tf32(av0.x); As[nb][ac + 1][ar] = cvt_tf32(av0.y);
            As[nb][ac + 2][ar] = cvt_tf32(av0.z); As[nb][ac + 3][ar] = cvt_tf32(av0.w);
            As[nb][ac + 4][ar] = cvt_tf32(av1.x); As[nb][ac + 5][ar] = cvt_tf32(av1.y);
            As[nb][ac + 6][ar] = cvt_tf32(av1.z); As[nb][ac + 7][ar] = cvt_tf32(av1.w);
            #pragma unroll
            for (int j = 0; j < 8; j++)
                Bs[nb][br][bcn + 16 * j] = cvt_tf32(bvr[j]);
            __syncthreads();
            buf = nb;
        }
    }

    // ---- epilogue: add bias, store to g_Xp ----
    #pragma unroll
    for (int mt = 0; mt < 4; mt++) {
        #pragma unroll
        for (int nt = 0; nt < 4; nt++) {
            const int colg = wn * 32 + nt * 8 + 2 * qk;       // within 128 tile
            const float bx0 = bb[col0 + colg];
            const float bx1 = bb[col0 + colg + 1];
            const size_t row0 = (size_t)(bm + wm * 64 + mt * 16 + qg);
            float2 v0 = make_float2(c[mt][nt][0] + bx0, c[mt][nt][1] + bx1);
            float2 v1 = make_float2(c[mt][nt][2] + bx0, c[mt][nt][3] + bx1);
            *(float2*)&g_Xp[row0 * N4 + bn + colg]       = v0;
            *(float2*)&g_Xp[(row0 + 8) * N4 + bn + colg] = v1;
        }
    }
}

// ---------------- fused per-step (tf32 mma): gates = Xp + H @ Wh ------------
// grid 128, 128 threads (4 warps). Block tile: all 64 batch rows x 8 hidden
// cols x 4 gates (= 64x32 gate-cols), K = 1024. Warp tile 32x16 (2x2 warps).
// As[m][k] pad 34 (STS.64 2-way, frag 2-way worst); Bs[k][gc] pad 36
// (frag conflict-free, STS.128). Fused LSTM cell epilogue via sg staging.
__global__ __launch_bounds__(128)
void lstm_step_tf32(const float* __restrict__ Hprev,
                    const float* __restrict__ W0, const float* __restrict__ W1,
                    const float* __restrict__ W2, const float* __restrict__ W3,
                    int t,
                    float* __restrict__ Hout) {
    __shared__ uint32_t As[2][64][34];   // [buf][m 0..63][k 0..31]
    __shared__ uint32_t Bs[2][32][36];   // [buf][k 0..31][gc = g*8+c]
    __shared__ float    sg[64][33];      // [row][gc] gate staging

    const int tid  = threadIdx.x;
    const int lane = tid & 31;
    const int warp = tid >> 5;           // 0..3
    const int colbase = blockIdx.x * 8;  // hidden cols [colbase, colbase+8)

    const float* Xp_t = g_Xp + (size_t)t * BATCH * N4;
    const float* Ws[4] = {W0, W1, W2, W3};

    const int wm = warp >> 1;            // rows 32*wm
    const int wn = warp & 1;             // gate-cols 16*wn
    const int qg = lane >> 2;
    const int qk = lane & 3;

    // H loader: k = 2*k2, rows rh + 8i (8 float2 per thread per tile)
    const int k2 = tid & 15;
    const int rh = tid >> 4;             // 0..7
    // W loader: 2 float4 per thread per tile
    const int lc4 = tid & 1;             // float4 slot within 8 cols
    const int lg  = (tid >> 1) & 3;      // gate
    const int lkw = tid >> 3;            // k row 0..15 (+16*it)

    float c[2][2][4];
    #pragma unroll
    for (int mt = 0; mt < 2; mt++)
        #pragma unroll
        for (int nt = 0; nt < 2; nt++)
            #pragma unroll
            for (int r = 0; r < 4; r++) c[mt][nt][r] = 0.0f;

    // ---- preload k-tile 0 ----
    #pragma unroll
    for (int i = 0; i < 8; i++) {
        float2 h = *(const float2*)&Hprev[(size_t)(rh + 8 * i) * HID + 2 * k2];
        As[0][rh + 8 * i][2 * k2]     = cvt_tf32(h.x);
        As[0][rh + 8 * i][2 * k2 + 1] = cvt_tf32(h.y);
    }
    #pragma unroll
    for (int it = 0; it < 2; it++) {
        float4 w = *(const float4*)&Ws[lg][(size_t)(lkw + 16 * it) * HID + colbase + 4 * lc4];
        uint32_t* p = &Bs[0][lkw + 16 * it][lg * 8 + 4 * lc4];
        p[0] = cvt_tf32(w.x); p[1] = cvt_tf32(w.y);
        p[2] = cvt_tf32(w.z); p[3] = cvt_tf32(w.w);
    }
    __syncthreads();

    int buf = 0;
    for (int kt = 0; kt < HID / 32; kt++) {
        float2 hreg[8];
        float4 wreg[2];
        const int k0n = (kt + 1) * 32;
        const bool has_next = (kt + 1 < HID / 32);
        if (has_next) {
            #pragma unroll
            for (int i = 0; i < 8; i++)
                hreg[i] = *(const float2*)&Hprev[(size_t)(rh + 8 * i) * HID + k0n + 2 * k2];
            #pragma unroll
            for (int it = 0; it < 2; it++)
                wreg[it] = *(const float4*)&Ws[lg][(size_t)(k0n + lkw + 16 * it) * HID
                                                   + colbase + 4 * lc4];
        }

        #pragma unroll
        for (int kk = 0; kk < 32; kk += 8) {
            uint32_t af[2][4];
            #pragma unroll
            for (int mt = 0; mt < 2; mt++) {
                const int m = 32 * wm + 16 * mt;
                af[mt][0] = As[buf][m + qg][kk + qk];
                af[mt][1] = As[buf][m + qg + 8][kk + qk];
                af[mt][2] = As[buf][m + qg][kk + qk + 4];
                af[mt][3] = As[buf][m + qg + 8][kk + qk + 4];
            }
            uint32_t bf[2][2];
            #pragma unroll
            for (int nt = 0; nt < 2; nt++) {
                const int n = 16 * wn + 8 * nt;
                bf[nt][0] = Bs[buf][kk + qk][n + qg];
                bf[nt][1] = Bs[buf][kk + qk + 4][n + qg];
            }
            #pragma unroll
            for (int mt = 0; mt < 2; mt++)
                #pragma unroll
                for (int nt = 0; nt < 2; nt++)
                    mma_tf32(c[mt][nt][0], c[mt][nt][1], c[mt][nt][2], c[mt][nt][3],
                             af[mt][0], af[mt][1], af[mt][2], af[mt][3],
                             bf[nt][0], bf[nt][1]);
        }

        if (has_next) {
            const int nb = buf ^ 1;
            #pragma unroll
            for (int i = 0; i < 8; i++) {
                As[nb][rh + 8 * i][2 * k2]     = cvt_tf32(hreg[i].x);
                As[nb][rh + 8 * i][2 * k2 + 1] = cvt_tf32(hreg[i].y);
            }
            #pragma unroll
            for (int it = 0; it < 2; it++) {
                uint32_t* p = &Bs[nb][lkw + 16 * it][lg * 8 + 4 * lc4];
                p[0] = cvt_tf32(wreg[it].x); p[1] = cvt_tf32(wreg[it].y);
                p[2] = cvt_tf32(wreg[it].z); p[3] = cvt_tf32(wreg[it].w);
            }
            __syncthreads();
            buf = nb;
        }
    }

    // ---- stash gate partials ----
    #pragma unroll
    for (int mt = 0; mt < 2; mt++) {
        #pragma unroll
        for (int nt = 0; nt < 2; nt++) {
            const int row = 32 * wm + 16 * mt + qg;
            const int cn  = 16 * wn + 8 * nt + 2 * qk;
            sg[row][cn]         = c[mt][nt][0];
            sg[row][cn + 1]     = c[mt][nt][1];
            sg[row + 8][cn]     = c[mt][nt][2];
            sg[row + 8][cn + 1] = c[mt][nt][3];
        }
    }
    __syncthreads();

    // ---- fused LSTM cell epilogue: 64 rows x 8 cols = 512 cells, 4/thread ----
    #pragma unroll
    for (int i = 0; i < 4; i++) {
        const int cell = tid + 128 * i;
        const int row  = cell >> 3;        // 0..63
        const int cc   = cell & 7;         // 0..7
        const size_t xb = (size_t)row * N4 + colbase + cc;

        float gi = sg[row][0  + cc] + Xp_t[xb + 0 * HID];
        float gf = sg[row][8  + cc] + Xp_t[xb + 1 * HID];
        float go = sg[row][16 + cc] + Xp_t[xb + 2 * HID];
        float gg = sg[row][24 + cc] + Xp_t[xb + 3 * HID];

        float I = 1.0f / (1.0f + __expf(-gi));
        float F = 1.0f / (1.0f + __expf(-gf));
        float O = 1.0f / (1.0f + __expf(-go));
        float G = tanhf(gg);

        const int idx = row * HID + colbase + cc;
        float cn2 = fmaf(F, g_C[idx], I * G);
        g_C[idx] = cn2;
        Hout[idx] = O * tanhf(cn2);
    }
}

// ---------------- tail: H_f and C_f after outputs ---------------------------
__global__ void finalize_kernel(float* __restrict__ out) {
    int i = blockIdx.x * 256 + threadIdx.x;
    if (i < BATCH * HID) {
        size_t base = (size_t)T_STEPS * BATCH * HID;
        out[base + i] = out[(size_t)(T_STEPS - 1) * BATCH * HID + i];  // H_f
        out[base + BATCH * HID + i] = g_C[i];                          // C_f
    }
}

// ---------------- launch -----------------------------------------------------
extern "C" void kernel_launch(void* const* d_in, const int* in_sizes, int n_in,
                              void* d_out, int out_size) {
    const float* X   = (const float*)d_in[0];
    const float* H0  = (const float*)d_in[1];
    const float* C0  = (const float*)d_in[2];
    const float* Wxi = (const float*)d_in[3];
    const float* Wxf = (const float*)d_in[4];
    const float* Wxo = (const float*)d_in[5];
    const float* Wxc = (const float*)d_in[6];
    const float* Whi = (const float*)d_in[7];
    const float* Whf = (const float*)d_in[8];
    const float* Who = (const float*)d_in[9];
    const float* Whc = (const float*)d_in[10];
    const float* bi  = (const float*)d_in[11];
    const float* bf  = (const float*)d_in[12];
    const float* bo  = (const float*)d_in[13];
    const float* bc  = (const float*)d_in[14];
    float* out = (float*)d_out;

    init_c_kernel<<<256, 256>>>(C0);
    xproj_tf32_kernel<<<dim3(32, 256), 256>>>(X, Wxi, Wxf, Wxo, Wxc,
                                              bi, bf, bo, bc);

    const float* Hprev = H0;
    for (int t = 0; t < T_STEPS; t++) {
        float* Hout = out + (size_t)t * BATCH * HID;
        lstm_step_tf32<<<128, 128>>>(Hprev, Whi, Whf, Who, Whc, t, Hout);
        Hprev = Hout;
    }
    finalize_kernel<<<256, 256>>>(out);
}

// round 9
// speedup vs baseline: 6.1032x; 1.1258x over previous
#include <cuda_runtime.h>
#include <math.h>
#include <stdint.h>

#define T_STEPS 512
#define BATCH   64
#define DIM     1024
#define HID     1024
#define N4      4096                 // 4 * HID
#define M_TOT   (T_STEPS * BATCH)    // 32768
#define NBLK    128                  // persistent blocks (<=148 SMs, 1/SM)

// ---------------- scratch (static device globals; no runtime allocation) ----
__device__ float g_Xp[(size_t)M_TOT * N4];   // 512 MB: X @ Wx + b, [T*B, 4H]
__device__ float g_C[BATCH * HID];           // cell state
__device__ unsigned int g_bar;               // software grid barrier counter

// ---------------- init cell state + barrier ---------------------------------
__global__ void init_c_kernel(const float* __restrict__ C0) {
    int i = blockIdx.x * 256 + threadIdx.x;
    if (i < BATCH * HID) g_C[i] = C0[i];
    if (i == 0) g_bar = 0u;
}

// ---------------- tf32 helpers ----------------------------------------------
__device__ __forceinline__ uint32_t cvt_tf32(float x) {
    uint32_t r;
    asm("cvt.rna.tf32.f32 %0, %1;" : "=r"(r) : "f"(x));
    return r;
}

__device__ __forceinline__ void mma_tf32(float& c0, float& c1, float& c2, float& c3,
                                         uint32_t a0, uint32_t a1, uint32_t a2, uint32_t a3,
                                         uint32_t b0, uint32_t b1) {
    asm volatile(
        "mma.sync.aligned.m16n8k8.row.col.f32.tf32.tf32.f32 "
        "{%0,%1,%2,%3}, {%4,%5,%6,%7}, {%8,%9}, {%0,%1,%2,%3};\n"
        : "+f"(c0), "+f"(c1), "+f"(c2), "+f"(c3)
        : "r"(a0), "r"(a1), "r"(a2), "r"(a3), "r"(b0), "r"(b1));
}

// acquire load of the barrier counter (gpu scope)
__device__ __forceinline__ unsigned bar_ld_acquire(const unsigned* p) {
    unsigned v;
    asm volatile("ld.global.acquire.gpu.u32 %0, [%1];" : "=r"(v) : "l"(p) : "memory");
    return v;
}

// release-add (no return) to the barrier counter (gpu scope)
__device__ __forceinline__ void bar_red_release(unsigned* p, unsigned v) {
    asm volatile("red.release.gpu.global.add.u32 [%0], %1;" :: "l"(p), "r"(v) : "memory");
}

__device__ __forceinline__ void fence_acq_rel_gpu() {
    asm volatile("fence.acq_rel.gpu;" ::: "memory");
}

// ---------------- big GEMM (tf32 tensor cores): g_Xp = X @ Wx + b ------------
// 128x128 output tile per block, BK=16, 256 threads = 8 warps (2x4 warp grid),
// each warp 64x32 via 4x4 m16n8k8 fragments. Pad 136 (== 8 mod 32).
__global__ __launch_bounds__(256)
void xproj_tf32_kernel(const float* __restrict__ X,
                       const float* __restrict__ W0, const float* __restrict__ W1,
                       const float* __restrict__ W2, const float* __restrict__ W3,
                       const float* __restrict__ b0, const float* __restrict__ b1,
                       const float* __restrict__ b2, const float* __restrict__ b3) {
    const int bn = blockIdx.x * 128;
    const int bm = blockIdx.y * 128;
    const int gate = bn >> 10;
    const float* W  = (gate == 0) ? W0 : (gate == 1) ? W1 : (gate == 2) ? W2 : W3;
    const float* bb = (gate == 0) ? b0 : (gate == 1) ? b1 : (gate == 2) ? b2 : b3;
    const int col0 = bn & (HID - 1);

    __shared__ uint32_t As[2][16][136];
    __shared__ uint32_t Bs[2][16][136];

    const int tid  = threadIdx.x;
    const int lane = tid & 31;
    const int warp = tid >> 5;
    const int wm   = warp >> 2;
    const int wn   = warp & 3;
    const int qg   = lane >> 2;
    const int qk   = lane & 3;

    const int ar  = tid >> 1;
    const int ac  = (tid & 1) * 8;
    const int br  = tid >> 4;
    const int bcn = tid & 15;

    float c[4][4][4];
    #pragma unroll
    for (int mt = 0; mt < 4; mt++)
        #pragma unroll
        for (int nt = 0; nt < 4; nt++)
            #pragma unroll
            for (int r = 0; r < 4; r++) c[mt][nt][r] = 0.0f;

    {
        float4 av0 = *(const float4*)&X[(size_t)(bm + ar) * DIM + ac];
        float4 av1 = *(const float4*)&X[(size_t)(bm + ar) * DIM + ac + 4];
        As[0][ac + 0][ar] = cvt_tf32(av0.x); As[0][ac + 1][ar] = cvt_tf32(av0.y);
        As[0][ac + 2][ar] = cvt_tf32(av0.z); As[0][ac + 3][ar] = cvt_tf32(av0.w);
        As[0][ac + 4][ar] = cvt_tf32(av1.x); As[0][ac + 5][ar] = cvt_tf32(av1.y);
        As[0][ac + 6][ar] = cvt_tf32(av1.z); As[0][ac + 7][ar] = cvt_tf32(av1.w);
        #pragma unroll
        for (int j = 0; j < 8; j++)
            Bs[0][br][bcn + 16 * j] =
                cvt_tf32(W[(size_t)br * HID + col0 + bcn + 16 * j]);
    }
    __syncthreads();

    int buf = 0;
    for (int kt = 0; kt < DIM / 16; kt++) {
        float4 av0, av1;
        float bvr[8];
        const int k0n = (kt + 1) * 16;
        const bool has_next = (kt + 1 < DIM / 16);
        if (has_next) {
            av0 = *(const float4*)&X[(size_t)(bm + ar) * DIM + k0n + ac];
            av1 = *(const float4*)&X[(size_t)(bm + ar) * DIM + k0n + ac + 4];
            #pragma unroll
            for (int j = 0; j < 8; j++)
                bvr[j] = W[(size_t)(k0n + br) * HID + col0 + bcn + 16 * j];
        }

        #pragma unroll
        for (int k8 = 0; k8 < 16; k8 += 8) {
            uint32_t af[4][4];
            #pragma unroll
            for (int mt = 0; mt < 4; mt++) {
                const int m = wm * 64 + mt * 16 + qg;
                af[mt][0] = As[buf][k8 + qk][m];
                af[mt][1] = As[buf][k8 + qk][m + 8];
                af[mt][2] = As[buf][k8 + 4 + qk][m];
                af[mt][3] = As[buf][k8 + 4 + qk][m + 8];
            }
            uint32_t bf[4][2];
            #pragma unroll
            for (int nt = 0; nt < 4; nt++) {
                const int n = wn * 32 + nt * 8 + qg;
                bf[nt][0] = Bs[buf][k8 + qk][n];
                bf[nt][1] = Bs[buf][k8 + 4 + qk][n];
            }
            #pragma unroll
            for (int mt = 0; mt < 4; mt++)
                #pragma unroll
                for (int nt = 0; nt < 4; nt++)
                    mma_tf32(c[mt][nt][0], c[mt][nt][1], c[mt][nt][2], c[mt][nt][3],
                             af[mt][0], af[mt][1], af[mt][2], af[mt][3],
                             bf[nt][0], bf[nt][1]);
        }

        if (has_next) {
            const int nb = buf ^ 1;
            As[nb][ac + 0][ar] = cvt_tf32(av0.x); As[nb][ac + 1][ar] = cvt_tf32(av0.y);
            As[nb][ac + 2][ar] = cvt_tf32(av0.z); As[nb][ac + 3][ar] = cvt_tf32(av0.w);
            As[nb][ac + 4][ar] = cvt_tf32(av1.x); As[nb][ac + 5][ar] = cvt_tf32(av1.y);
            As[nb][ac + 6][ar] = cvt_tf32(av1.z); As[nb][ac + 7][ar] = cvt_tf32(av1.w);
            #pragma unroll
            for (int j = 0; j < 8; j++)
                Bs[nb][br][bcn + 16 * j] = cvt_tf32(bvr[j]);
            __syncthreads();
            buf = nb;
        }
    }

    #pragma unroll
    for (int mt = 0; mt < 4; mt++) {
        #pragma unroll
        for (int nt = 0; nt < 4; nt++) {
            const int colg = wn * 32 + nt * 8 + 2 * qk;
            const float bx0 = bb[col0 + colg];
            const float bx1 = bb[col0 + colg + 1];
            const size_t row0 = (size_t)(bm + wm * 64 + mt * 16 + qg);
            float2 v0 = make_float2(c[mt][nt][0] + bx0, c[mt][nt][1] + bx1);
            float2 v1 = make_float2(c[mt][nt][2] + bx0, c[mt][nt][3] + bx1);
            *(float2*)&g_Xp[row0 * N4 + bn + colg]       = v0;
            *(float2*)&g_Xp[(row0 + 8) * N4 + bn + colg] = v1;
        }
    }
}

// ---------------- persistent recurrence kernel -------------------------------
// 128 blocks x 128 threads, 1 block/SM (all co-resident). Each block owns
// hidden cols [8*bid, 8*bid+8) for all 4 gates and all 64 batch rows.
// Wh for those columns (tf32) lives in smem for the whole kernel (147 KB).
// Per step: stream H(t-1) from L2 (ldcg), tf32 mma, fused LSTM epilogue,
// then a grid barrier with full release/acquire semantics.
#define WS_WORDS (32 * 32 * 36)          // [ktile][k][gc]
#define AS_WORDS (2 * 64 * 34)           // [buf][m][k]
#define SMEM_BYTES ((WS_WORDS + AS_WORDS) * 4 + 64 * 33 * 4)

__global__ __launch_bounds__(128)
void lstm_persistent(const float* __restrict__ H0,
                     const float* __restrict__ W0, const float* __restrict__ W1,
                     const float* __restrict__ W2, const float* __restrict__ W3,
                     float* __restrict__ out) {
    extern __shared__ unsigned char smem_raw[];
    uint32_t (*Ws)[32][36] = (uint32_t (*)[32][36])smem_raw;                 // [32][32][36]
    uint32_t (*As)[64][34] = (uint32_t (*)[64][34])(smem_raw + WS_WORDS * 4);// [2][64][34]
    float    (*sg)[33]     = (float (*)[33])(smem_raw + (WS_WORDS + AS_WORDS) * 4);

    const int tid  = threadIdx.x;
    const int lane = tid & 31;
    const int warp = tid >> 5;
    const int colbase = blockIdx.x * 8;

    const float* Wg[4] = {W0, W1, W2, W3};

    const int wm = warp >> 1;
    const int wn = warp & 1;
    const int qg = lane >> 2;
    const int qk = lane & 3;

    // H loader mapping
    const int k2 = tid & 15;
    const int rh = tid >> 4;
    // W loader mapping
    const int lc4 = tid & 1;
    const int lg  = (tid >> 1) & 3;
    const int lkw = tid >> 3;            // 0..15

    // ---- load resident W (once) ----
    for (int kt = 0; kt < 32; kt++) {
        #pragma unroll
        for (int it = 0; it < 2; it++) {
            float4 w = *(const float4*)&Wg[lg][(size_t)(kt * 32 + lkw + 16 * it) * HID
                                               + colbase + 4 * lc4];
            uint32_t* p = &Ws[kt][lkw + 16 * it][lg * 8 + 4 * lc4];
            p[0] = cvt_tf32(w.x); p[1] = cvt_tf32(w.y);
            p[2] = cvt_tf32(w.z); p[3] = cvt_tf32(w.w);
        }
    }
    __syncthreads();

    for (int t = 0; t < T_STEPS; t++) {
        const float* Hprev = (t == 0) ? H0 : out + (size_t)(t - 1) * BATCH * HID;
        const float* Xp_t  = g_Xp + (size_t)t * BATCH * N4;
        float* Hout = out + (size_t)t * BATCH * HID;

        float c[2][2][4];
        #pragma unroll
        for (int mt = 0; mt < 2; mt++)
            #pragma unroll
            for (int nt = 0; nt < 2; nt++)
                #pragma unroll
                for (int r = 0; r < 4; r++) c[mt][nt][r] = 0.0f;

        // preload H k-tile 0 (ldcg: L2 read, cross-SM coherent)
        #pragma unroll
        for (int i = 0; i < 8; i++) {
            float2 h = __ldcg((const float2*)&Hprev[(size_t)(rh + 8 * i) * HID + 2 * k2]);
            As[0][rh + 8 * i][2 * k2]     = cvt_tf32(h.x);
            As[0][rh + 8 * i][2 * k2 + 1] = cvt_tf32(h.y);
        }
        __syncthreads();

        int buf = 0;
        for (int kt = 0; kt < HID / 32; kt++) {
            float2 hreg[8];
            const int k0n = (kt + 1) * 32;
            const bool has_next = (kt + 1 < HID / 32);
            if (has_next) {
                #pragma unroll
                for (int i = 0; i < 8; i++)
                    hreg[i] = __ldcg((const float2*)&Hprev[(size_t)(rh + 8 * i) * HID
                                                           + k0n + 2 * k2]);
            }

            #pragma unroll
            for (int kk = 0; kk < 32; kk += 8) {
                uint32_t af[2][4];
                #pragma unroll
                for (int mt = 0; mt < 2; mt++) {
                    const int m = 32 * wm + 16 * mt;
                    af[mt][0] = As[buf][m + qg][kk + qk];
                    af[mt][1] = As[buf][m + qg + 8][kk + qk];
                    af[mt][2] = As[buf][m + qg][kk + qk + 4];
                    af[mt][3] = As[buf][m + qg + 8][kk + qk + 4];
                }
                uint32_t bf[2][2];
                #pragma unroll
                for (int nt = 0; nt < 2; nt++) {
                    const int n = 16 * wn + 8 * nt;
                    bf[nt][0] = Ws[kt][kk + qk][n + qg];
                    bf[nt][1] = Ws[kt][kk + qk + 4][n + qg];
                }
                #pragma unroll
                for (int mt = 0; mt < 2; mt++)
                    #pragma unroll
                    for (int nt = 0; nt < 2; nt++)
                        mma_tf32(c[mt][nt][0], c[mt][nt][1], c[mt][nt][2], c[mt][nt][3],
                                 af[mt][0], af[mt][1], af[mt][2], af[mt][3],
                                 bf[nt][0], bf[nt][1]);
            }

            if (has_next) {
                const int nb = buf ^ 1;
                __syncthreads();   // all warps done reading As[nb] (prev use)
                #pragma unroll
                for (int i = 0; i < 8; i++) {
                    As[nb][rh + 8 * i][2 * k2]     = cvt_tf32(hreg[i].x);
                    As[nb][rh + 8 * i][2 * k2 + 1] = cvt_tf32(hreg[i].y);
                }
                __syncthreads();
                buf = nb;
            }
        }

        // stash gate partials
        #pragma unroll
        for (int mt = 0; mt < 2; mt++) {
            #pragma unroll
            for (int nt = 0; nt < 2; nt++) {
                const int row = 32 * wm + 16 * mt + qg;
                const int cn  = 16 * wn + 8 * nt + 2 * qk;
                sg[row][cn]         = c[mt][nt][0];
                sg[row][cn + 1]     = c[mt][nt][1];
                sg[row + 8][cn]     = c[mt][nt][2];
                sg[row + 8][cn + 1] = c[mt][nt][3];
            }
        }
        __syncthreads();

        // fused LSTM cell epilogue: 64 rows x 8 cols, 4 cells/thread
        #pragma unroll
        for (int i = 0; i < 4; i++) {
            const int cell = tid + 128 * i;
            const int row  = cell >> 3;
            const int cc   = cell & 7;
            const size_t xb = (size_t)row * N4 + colbase + cc;

            float gi = sg[row][0  + cc] + Xp_t[xb + 0 * HID];
            float gf = sg[row][8  + cc] + Xp_t[xb + 1 * HID];
            float go = sg[row][16 + cc] + Xp_t[xb + 2 * HID];
            float gg = sg[row][24 + cc] + Xp_t[xb + 3 * HID];

            float I = 1.0f / (1.0f + __expf(-gi));
            float F = 1.0f / (1.0f + __expf(-go * 0.0f - gf));   // sigmoid(gf)
            float O = 1.0f / (1.0f + __expf(-go));
            float G = tanhf(gg);

            const int idx = row * HID + colbase + cc;
            float cn2 = fmaf(F, g_C[idx], I * G);
            g_C[idx] = cn2;
            __stcg(&Hout[idx], O * tanhf(cn2));   // straight to L2
        }

        // ---- grid barrier: release(all stores) -> arrive -> acquire spin ----
        __threadfence();                 // each thread releases its stores
        __syncthreads();                 // all threads' fences done
        if (tid == 0) {
            bar_red_release(&g_bar, 1u); // release arrival
            const unsigned target = (unsigned)NBLK * (unsigned)(t + 1);
            while (bar_ld_acquire(&g_bar) < target) {}
        }
        __syncthreads();                 // broadcast release from spin
        fence_acq_rel_gpu();             // acquire for ALL threads' later loads
    }
}

// ---------------- tail: H_f and C_f after outputs ---------------------------
__global__ void finalize_kernel(float* __restrict__ out) {
    int i = blockIdx.x * 256 + threadIdx.x;
    if (i < BATCH * HID) {
        size_t base = (size_t)T_STEPS * BATCH * HID;
        out[base + i] = out[(size_t)(T_STEPS - 1) * BATCH * HID + i];  // H_f
        out[base + BATCH * HID + i] = g_C[i];                          // C_f
    }
}

// ---------------- launch -----------------------------------------------------
extern "C" void kernel_launch(void* const* d_in, const int* in_sizes, int n_in,
                              void* d_out, int out_size) {
    const float* X   = (const float*)d_in[0];
    const float* H0  = (const float*)d_in[1];
    const float* C0  = (const float*)d_in[2];
    const float* Wxi = (const float*)d_in[3];
    const float* Wxf = (const float*)d_in[4];
    const float* Wxo = (const float*)d_in[5];
    const float* Wxc = (const float*)d_in[6];
    const float* Whi = (const float*)d_in[7];
    const float* Whf = (const float*)d_in[8];
    const float* Who = (const float*)d_in[9];
    const float* Whc = (const float*)d_in[10];
    const float* bi  = (const float*)d_in[11];
    const float* bf  = (const float*)d_in[12];
    const float* bo  = (const float*)d_in[13];
    const float* bc  = (const float*)d_in[14];
    float* out = (float*)d_out;

    cudaFuncSetAttribute(lstm_persistent,
                         cudaFuncAttributeMaxDynamicSharedMemorySize, SMEM_BYTES);

    init_c_kernel<<<256, 256>>>(C0);
    xproj_tf32_kernel<<<dim3(32, 256), 256>>>(X, Wxi, Wxf, Wxo, Wxc,
                                              bi, bf, bo, bc);
    lstm_persistent<<<NBLK, 128, SMEM_BYTES>>>(H0, Whi, Whf, Who, Whc, out);
    finalize_kernel<<<256, 256>>>(out);
}

// round 10
// speedup vs baseline: 6.8282x; 1.1188x over previous
#include <cuda_runtime.h>
#include <math.h>
#include <stdint.h>

#define T_STEPS 512
#define BATCH   64
#define DIM     1024
#define HID     1024
#define N4      4096                 // 4 * HID
#define M_TOT   (T_STEPS * BATCH)    // 32768
#define NBLK    128                  // persistent blocks (<=148 SMs, 1/SM)

// ---------------- scratch (static device globals; no runtime allocation) ----
__device__ float g_Xp[(size_t)M_TOT * N4];   // 512 MB: X @ Wx + b, [T*B, 4H]
__device__ float g_C[BATCH * HID];           // cell state
__device__ unsigned int g_bar;               // software grid barrier counter

// ---------------- init cell state + barrier ---------------------------------
__global__ void init_c_kernel(const float* __restrict__ C0) {
    int i = blockIdx.x * 256 + threadIdx.x;
    if (i < BATCH * HID) g_C[i] = C0[i];
    if (i == 0) g_bar = 0u;
}

// ---------------- tf32 helpers ----------------------------------------------
__device__ __forceinline__ uint32_t cvt_tf32(float x) {
    uint32_t r;
    asm("cvt.rna.tf32.f32 %0, %1;" : "=r"(r) : "f"(x));
    return r;
}

__device__ __forceinline__ void mma_tf32(float& c0, float& c1, float& c2, float& c3,
                                         uint32_t a0, uint32_t a1, uint32_t a2, uint32_t a3,
                                         uint32_t b0, uint32_t b1) {
    asm volatile(
        "mma.sync.aligned.m16n8k8.row.col.f32.tf32.tf32.f32 "
        "{%0,%1,%2,%3}, {%4,%5,%6,%7}, {%8,%9}, {%0,%1,%2,%3};\n"
        : "+f"(c0), "+f"(c1), "+f"(c2), "+f"(c3)
        : "r"(a0), "r"(a1), "r"(a2), "r"(a3), "r"(b0), "r"(b1));
}

__device__ __forceinline__ unsigned bar_ld_acquire(const unsigned* p) {
    unsigned v;
    asm volatile("ld.global.acquire.gpu.u32 %0, [%1];" : "=r"(v) : "l"(p) : "memory");
    return v;
}
__device__ __forceinline__ void bar_red_release(unsigned* p, unsigned v) {
    asm volatile("red.release.gpu.global.add.u32 [%0], %1;" :: "l"(p), "r"(v) : "memory");
}
__device__ __forceinline__ void fence_acq_rel_gpu() {
    asm volatile("fence.acq_rel.gpu;" ::: "memory");
}

// paired-k index: (k, k+4) stored adjacently within each 8-k group.
// idx(k) = (k & ~7) | ((k & 3) << 1) | ((k >> 2) & 1)
__device__ __forceinline__ int kpair_idx(int k) {
    return (k & ~7) | ((k & 3) << 1) | ((k >> 2) & 1);
}

// ---------------- big GEMM (tf32 tensor cores): g_Xp = X @ Wx + b ------------
__global__ __launch_bounds__(256)
void xproj_tf32_kernel(const float* __restrict__ X,
                       const float* __restrict__ W0, const float* __restrict__ W1,
                       const float* __restrict__ W2, const float* __restrict__ W3,
                       const float* __restrict__ b0, const float* __restrict__ b1,
                       const float* __restrict__ b2, const float* __restrict__ b3) {
    const int bn = blockIdx.x * 128;
    const int bm = blockIdx.y * 128;
    const int gate = bn >> 10;
    const float* W  = (gate == 0) ? W0 : (gate == 1) ? W1 : (gate == 2) ? W2 : W3;
    const float* bb = (gate == 0) ? b0 : (gate == 1) ? b1 : (gate == 2) ? b2 : b3;
    const int col0 = bn & (HID - 1);

    __shared__ uint32_t As[2][16][136];
    __shared__ uint32_t Bs[2][16][136];

    const int tid  = threadIdx.x;
    const int lane = tid & 31;
    const int warp = tid >> 5;
    const int wm   = warp >> 2;
    const int wn   = warp & 3;
    const int qg   = lane >> 2;
    const int qk   = lane & 3;

    const int ar  = tid >> 1;
    const int ac  = (tid & 1) * 8;
    const int br  = tid >> 4;
    const int bcn = tid & 15;

    float c[4][4][4];
    #pragma unroll
    for (int mt = 0; mt < 4; mt++)
        #pragma unroll
        for (int nt = 0; nt < 4; nt++)
            #pragma unroll
            for (int r = 0; r < 4; r++) c[mt][nt][r] = 0.0f;

    {
        float4 av0 = *(const float4*)&X[(size_t)(bm + ar) * DIM + ac];
        float4 av1 = *(const float4*)&X[(size_t)(bm + ar) * DIM + ac + 4];
        As[0][ac + 0][ar] = cvt_tf32(av0.x); As[0][ac + 1][ar] = cvt_tf32(av0.y);
        As[0][ac + 2][ar] = cvt_tf32(av0.z); As[0][ac + 3][ar] = cvt_tf32(av0.w);
        As[0][ac + 4][ar] = cvt_tf32(av1.x); As[0][ac + 5][ar] = cvt_tf32(av1.y);
        As[0][ac + 6][ar] = cvt_tf32(av1.z); As[0][ac + 7][ar] = cvt_tf32(av1.w);
        #pragma unroll
        for (int j = 0; j < 8; j++)
            Bs[0][br][bcn + 16 * j] =
                cvt_tf32(W[(size_t)br * HID + col0 + bcn + 16 * j]);
    }
    __syncthreads();

    int buf = 0;
    for (int kt = 0; kt < DIM / 16; kt++) {
        float4 av0, av1;
        float bvr[8];
        const int k0n = (kt + 1) * 16;
        const bool has_next = (kt + 1 < DIM / 16);
        if (has_next) {
            av0 = *(const float4*)&X[(size_t)(bm + ar) * DIM + k0n + ac];
            av1 = *(const float4*)&X[(size_t)(bm + ar) * DIM + k0n + ac + 4];
            #pragma unroll
            for (int j = 0; j < 8; j++)
                bvr[j] = W[(size_t)(k0n + br) * HID + col0 + bcn + 16 * j];
        }

        #pragma unroll
        for (int k8 = 0; k8 < 16; k8 += 8) {
            uint32_t af[4][4];
            #pragma unroll
            for (int mt = 0; mt < 4; mt++) {
                const int m = wm * 64 + mt * 16 + qg;
                af[mt][0] = As[buf][k8 + qk][m];
                af[mt][1] = As[buf][k8 + qk][m + 8];
                af[mt][2] = As[buf][k8 + 4 + qk][m];
                af[mt][3] = As[buf][k8 + 4 + qk][m + 8];
            }
            uint32_t bf[4][2];
            #pragma unroll
            for (int nt = 0; nt < 4; nt++) {
                const int n = wn * 32 + nt * 8 + qg;
                bf[nt][0] = Bs[buf][k8 + qk][n];
                bf[nt][1] = Bs[buf][k8 + 4 + qk][n];
            }
            #pragma unroll
            for (int mt = 0; mt < 4; mt++)
                #pragma unroll
                for (int nt = 0; nt < 4; nt++)
                    mma_tf32(c[mt][nt][0], c[mt][nt][1], c[mt][nt][2], c[mt][nt][3],
                             af[mt][0], af[mt][1], af[mt][2], af[mt][3],
                             bf[nt][0], bf[nt][1]);
        }

        if (has_next) {
            const int nb = buf ^ 1;
            As[nb][ac + 0][ar] = cvt_tf32(av0.x); As[nb][ac + 1][ar] = cvt_tf32(av0.y);
            As[nb][ac + 2][ar] = cvt_tf32(av0.z); As[nb][ac + 3][ar] = cvt_tf32(av0.w);
            As[nb][ac + 4][ar] = cvt_tf32(av1.x); As[nb][ac + 5][ar] = cvt_tf32(av1.y);
            As[nb][ac + 6][ar] = cvt_tf32(av1.z); As[nb][ac + 7][ar] = cvt_tf32(av1.w);
            #pragma unroll
            for (int j = 0; j < 8; j++)
                Bs[nb][br][bcn + 16 * j] = cvt_tf32(bvr[j]);
            __syncthreads();
            buf = nb;
        }
    }

    #pragma unroll
    for (int mt = 0; mt < 4; mt++) {
        #pragma unroll
        for (int nt = 0; nt < 4; nt++) {
            const int colg = wn * 32 + nt * 8 + 2 * qk;
            const float bx0 = bb[col0 + colg];
            const float bx1 = bb[col0 + colg + 1];
            const size_t row0 = (size_t)(bm + wm * 64 + mt * 16 + qg);
            float2 v0 = make_float2(c[mt][nt][0] + bx0, c[mt][nt][1] + bx1);
            float2 v1 = make_float2(c[mt][nt][2] + bx0, c[mt][nt][3] + bx1);
            *(float2*)&g_Xp[row0 * N4 + bn + colg]       = v0;
            *(float2*)&g_Xp[(row0 + 8) * N4 + bn + colg] = v1;
        }
    }
}

// ---------------- persistent recurrence kernel -------------------------------
// 128 blocks x 256 threads (8 warps), 1 block/SM. Each block owns hidden cols
// [8*bid, 8*bid+8) x 4 gates x all 64 batch rows. K split 2-way across warp
// groups (warps 0-3: K[0,512), warps 4-7: K[512,1024)); partials summed in
// the fused epilogue. Wh resident in smem in paired-k layout (LDS.64 frags).
//
// smem: Wp[32][16][33][2] (135 KB) + As[2][2][64][36] (73.7 KB)
//       + sg[2][64][33] (16.9 KB) = 225.8 KB
#define WP_WORDS (32 * 16 * 33 * 2)
#define AS_WORDS (2 * 2 * 64 * 36)
#define SG_WORDS (2 * 64 * 33)
#define SMEM_BYTES ((WP_WORDS + AS_WORDS + SG_WORDS) * 4)

__global__ __launch_bounds__(256)
void lstm_persistent(const float* __restrict__ H0,
                     const float* __restrict__ W0, const float* __restrict__ W1,
                     const float* __restrict__ W2, const float* __restrict__ W3,
                     float* __restrict__ out) {
    extern __shared__ unsigned char smem_raw[];
    uint32_t (*Wp)[16][33][2]  = (uint32_t (*)[16][33][2])smem_raw;
    uint32_t (*As)[2][64][36]  = (uint32_t (*)[2][64][36])(smem_raw + WP_WORDS * 4);
    float    (*sg)[64][33]     = (float (*)[64][33])(smem_raw + (WP_WORDS + AS_WORDS) * 4);

    const int tid  = threadIdx.x;
    const int lane = tid & 31;
    const int warp = tid >> 5;           // 0..7
    const int colbase = blockIdx.x * 8;

    const float* Wg[4] = {W0, W1, W2, W3};

    const int kg = warp >> 2;            // K-group 0/1 (matches tid>>7)
    const int wq = warp & 3;
    const int wm = wq >> 1;              // rows 32*wm
    const int wn = wq & 1;               // gate-cols 16*wn
    const int qg = lane >> 2;
    const int qk = lane & 3;

    // H loader mapping (within 128-thread half; half g loads K-group g)
    const int gtid = tid & 127;
    const int k2 = gtid & 15;            // k offset = 2*k2 within 32-tile
    const int rh = gtid >> 4;            // rows rh + 8i

    // ---- load resident W (once) into paired-k layout ----
    // warp w covers k rows w + 8*j; lane -> gate-col gc = lane (g = gc>>3, c = gc&7)
    {
        const int gcl = lane;
        const int gl  = gcl >> 3;
        const int cl  = gcl & 7;
        for (int j = 0; j < 128; j++) {
            const int k = warp + 8 * j;
            const float v = Wg[gl][(size_t)k * HID + colbase + cl];
            const int kt  = k >> 5;
            const int kin = k & 31;
            const int pp  = ((kin >> 3) << 2) | (kin & 3);
            const int sl  = (kin >> 2) & 1;
            Wp[kt][pp][gcl][sl] = cvt_tf32(v);
        }
    }
    __syncthreads();

    for (int t = 0; t < T_STEPS; t++) {
        const float* Hprev = (t == 0) ? H0 : out + (size_t)(t - 1) * BATCH * HID;
        const float* Xp_t  = g_Xp + (size_t)t * BATCH * N4;
        float* Hout = out + (size_t)t * BATCH * HID;

        float c[2][2][4];
        #pragma unroll
        for (int mt = 0; mt < 2; mt++)
            #pragma unroll
            for (int nt = 0; nt < 2; nt++)
                #pragma unroll
                for (int r = 0; r < 4; r++) c[mt][nt][r] = 0.0f;

        const int kbase = kg * 512;      // this half's K origin
        const int i0 = kpair_idx(2 * k2);        // store index for k even
        // idx(k+1) = idx(k) + 2 for even k

        // preload H k-tile 0 of this half (ldcg: L2, cross-SM coherent)
        #pragma unroll
        for (int i = 0; i < 8; i++) {
            float2 h = __ldcg((const float2*)&Hprev[(size_t)(rh + 8 * i) * HID
                                                    + kbase + 2 * k2]);
            As[kg][0][rh + 8 * i][i0]     = cvt_tf32(h.x);
            As[kg][0][rh + 8 * i][i0 + 2] = cvt_tf32(h.y);
        }
        __syncthreads();

        int buf = 0;
        for (int kt2 = 0; kt2 < 16; kt2++) {
            const int kt = kg * 16 + kt2;        // global k-tile for compute
            float2 hreg[8];
            const bool has_next = (kt2 + 1 < 16);
            if (has_next) {
                const int k0n = kbase + (kt2 + 1) * 32;
                #pragma unroll
                for (int i = 0; i < 8; i++)
                    hreg[i] = __ldcg((const float2*)&Hprev[(size_t)(rh + 8 * i) * HID
                                                           + k0n + 2 * k2]);
            }

            #pragma unroll
            for (int kk = 0; kk < 32; kk += 8) {
                // A fragments via paired LDS.64: (k=kk+qk, k=kk+qk+4)
                uint2 a0p[2], a1p[2];
                #pragma unroll
                for (int mt = 0; mt < 2; mt++) {
                    const int m = 32 * wm + 16 * mt;
                    a0p[mt] = *(const uint2*)&As[kg][buf][m + qg][kk + 2 * qk];
                    a1p[mt] = *(const uint2*)&As[kg][buf][m + qg + 8][kk + 2 * qk];
                }
                // B fragments: one LDS.64 each
                uint2 bp[2];
                #pragma unroll
                for (int nt = 0; nt < 2; nt++) {
                    const int n = 16 * wn + 8 * nt;
                    bp[nt] = *(const uint2*)&Wp[kt][((kk >> 3) << 2) | qk][n + qg][0];
                }
                #pragma unroll
                for (int mt = 0; mt < 2; mt++)
                    #pragma unroll
                    for (int nt = 0; nt < 2; nt++)
                        mma_tf32(c[mt][nt][0], c[mt][nt][1], c[mt][nt][2], c[mt][nt][3],
                                 a0p[mt].x, a1p[mt].x, a0p[mt].y, a1p[mt].y,
                                 bp[nt].x, bp[nt].y);
            }

            if (has_next) {
                const int nb = buf ^ 1;
                __syncthreads();   // all warps done reading As[*][nb] (prev use)
                #pragma unroll
                for (int i = 0; i < 8; i++) {
                    As[kg][nb][rh + 8 * i][i0]     = cvt_tf32(hreg[i].x);
                    As[kg][nb][rh + 8 * i][i0 + 2] = cvt_tf32(hreg[i].y);
                }
                __syncthreads();
                buf = nb;
            }
        }

        // stash per-K-group gate partials
        #pragma unroll
        for (int mt = 0; mt < 2; mt++) {
            #pragma unroll
            for (int nt = 0; nt < 2; nt++) {
                const int row = 32 * wm + 16 * mt + qg;
                const int cn  = 16 * wn + 8 * nt + 2 * qk;
                sg[kg][row][cn]         = c[mt][nt][0];
                sg[kg][row][cn + 1]     = c[mt][nt][1];
                sg[kg][row + 8][cn]     = c[mt][nt][2];
                sg[kg][row + 8][cn + 1] = c[mt][nt][3];
            }
        }
        __syncthreads();

        // fused LSTM cell epilogue: 64 rows x 8 cols, 2 cells/thread
        #pragma unroll
        for (int i = 0; i < 2; i++) {
            const int cell = tid + 256 * i;
            const int row  = cell >> 3;
            const int cc   = cell & 7;
            const size_t xb = (size_t)row * N4 + colbase + cc;

            float gi = sg[0][row][0  + cc] + sg[1][row][0  + cc] + Xp_t[xb + 0 * HID];
            float gf = sg[0][row][8  + cc] + sg[1][row][8  + cc] + Xp_t[xb + 1 * HID];
            float go = sg[0][row][16 + cc] + sg[1][row][16 + cc] + Xp_t[xb + 2 * HID];
            float gg = sg[0][row][24 + cc] + sg[1][row][24 + cc] + Xp_t[xb + 3 * HID];

            float I = 1.0f / (1.0f + __expf(-gi));
            float F = 1.0f / (1.0f + __expf(-gf));
            float O = 1.0f / (1.0f + __expf(-go));
            float G = tanhf(gg);

            const int idx = row * HID + colbase + cc;
            float cn2 = fmaf(F, g_C[idx], I * G);
            g_C[idx] = cn2;
            __stcg(&Hout[idx], O * tanhf(cn2));   // straight to L2
        }

        // ---- grid barrier: release(all stores) -> arrive -> acquire ----
        __threadfence();
        __syncthreads();
        if (tid == 0) {
            bar_red_release(&g_bar, 1u);
            const unsigned target = (unsigned)NBLK * (unsigned)(t + 1);
            while (bar_ld_acquire(&g_bar) < target) {}
        }
        __syncthreads();
        fence_acq_rel_gpu();
    }
}

// ---------------- tail: H_f and C_f after outputs ---------------------------
__global__ void finalize_kernel(float* __restrict__ out) {
    int i = blockIdx.x * 256 + threadIdx.x;
    if (i < BATCH * HID) {
        size_t base = (size_t)T_STEPS * BATCH * HID;
        out[base + i] = out[(size_t)(T_STEPS - 1) * BATCH * HID + i];  // H_f
        out[base + BATCH * HID + i] = g_C[i];                          // C_f
    }
}

// ---------------- launch -----------------------------------------------------
extern "C" void kernel_launch(void* const* d_in, const int* in_sizes, int n_in,
                              void* d_out, int out_size) {
    const float* X   = (const float*)d_in[0];
    const float* H0  = (const float*)d_in[1];
    const float* C0  = (const float*)d_in[2];
    const float* Wxi = (const float*)d_in[3];
    const float* Wxf = (const float*)d_in[4];
    const float* Wxo = (const float*)d_in[5];
    const float* Wxc = (const float*)d_in[6];
    const float* Whi = (const float*)d_in[7];
    const float* Whf = (const float*)d_in[8];
    const float* Who = (const float*)d_in[9];
    const float* Whc = (const float*)d_in[10];
    const float* bi  = (const float*)d_in[11];
    const float* bf  = (const float*)d_in[12];
    const float* bo  = (const float*)d_in[13];
    const float* bc  = (const float*)d_in[14];
    float* out = (float*)d_out;

    cudaFuncSetAttribute(lstm_persistent,
                         cudaFuncAttributeMaxDynamicSharedMemorySize, SMEM_BYTES);

    init_c_kernel<<<256, 256>>>(C0);
    xproj_tf32_kernel<<<dim3(32, 256), 256>>>(X, Wxi, Wxf, Wxo, Wxc,
                                              bi, bf, bo, bc);
    lstm_persistent<<<NBLK, 256, SMEM_BYTES>>>(H0, Whi, Whf, Who, Whc, out);
    finalize_kernel<<<256, 256>>>(out);
}

// round 11
// speedup vs baseline: 8.5726x; 1.2555x over previous
#include <cuda_runtime.h>
#include <cuda_fp16.h>
#include <math.h>
#include <stdint.h>

#define T_STEPS 512
#define BATCH   64
#define DIM     1024
#define HID     1024
#define N4      4096                 // 4 * HID
#define M_TOT   (T_STEPS * BATCH)    // 32768
#define NBLK    128                  // persistent blocks (<=148 SMs, 1/SM)

// ---------------- scratch (static device globals; no runtime allocation) ----
__device__ float g_Xp[(size_t)M_TOT * N4];   // 512 MB: X @ Wx + b, [T*B, 4H]
__device__ float g_C[BATCH * HID];           // cell state
__device__ unsigned int g_bar;               // software grid barrier counter

// ---------------- init cell state + barrier ---------------------------------
__global__ void init_c_kernel(const float* __restrict__ C0) {
    int i = blockIdx.x * 256 + threadIdx.x;
    if (i < BATCH * HID) g_C[i] = C0[i];
    if (i == 0) g_bar = 0u;
}

// ---------------- helpers ----------------------------------------------------
__device__ __forceinline__ uint32_t cvt_tf32(float x) {
    uint32_t r;
    asm("cvt.rna.tf32.f32 %0, %1;" : "=r"(r) : "f"(x));
    return r;
}

__device__ __forceinline__ uint32_t pack_h2(float lo, float hi) {
    __half2 h = __floats2half2_rn(lo, hi);   // x = lo, y = hi
    return *(uint32_t*)&h;
}

__device__ __forceinline__ void mma_tf32(float& c0, float& c1, float& c2, float& c3,
                                         uint32_t a0, uint32_t a1, uint32_t a2, uint32_t a3,
                                         uint32_t b0, uint32_t b1) {
    asm volatile(
        "mma.sync.aligned.m16n8k8.row.col.f32.tf32.tf32.f32 "
        "{%0,%1,%2,%3}, {%4,%5,%6,%7}, {%8,%9}, {%0,%1,%2,%3};\n"
        : "+f"(c0), "+f"(c1), "+f"(c2), "+f"(c3)
        : "r"(a0), "r"(a1), "r"(a2), "r"(a3), "r"(b0), "r"(b1));
}

__device__ __forceinline__ void mma_f16(float& c0, float& c1, float& c2, float& c3,
                                        uint32_t a0, uint32_t a1, uint32_t a2, uint32_t a3,
                                        uint32_t b0, uint32_t b1) {
    asm volatile(
        "mma.sync.aligned.m16n8k16.row.col.f32.f16.f16.f32 "
        "{%0,%1,%2,%3}, {%4,%5,%6,%7}, {%8,%9}, {%0,%1,%2,%3};\n"
        : "+f"(c0), "+f"(c1), "+f"(c2), "+f"(c3)
        : "r"(a0), "r"(a1), "r"(a2), "r"(a3), "r"(b0), "r"(b1));
}

__device__ __forceinline__ unsigned bar_ld_acquire(const unsigned* p) {
    unsigned v;
    asm volatile("ld.global.acquire.gpu.u32 %0, [%1];" : "=r"(v) : "l"(p) : "memory");
    return v;
}
__device__ __forceinline__ void bar_red_release(unsigned* p, unsigned v) {
    asm volatile("red.release.gpu.global.add.u32 [%0], %1;" :: "l"(p), "r"(v) : "memory");
}
__device__ __forceinline__ void fence_acq_rel_gpu() {
    asm volatile("fence.acq_rel.gpu;" ::: "memory");
}

// ---------------- big GEMM (tf32 tensor cores): g_Xp = X @ Wx + b ------------
__global__ __launch_bounds__(256)
void xproj_tf32_kernel(const float* __restrict__ X,
                       const float* __restrict__ W0, const float* __restrict__ W1,
                       const float* __restrict__ W2, const float* __restrict__ W3,
                       const float* __restrict__ b0, const float* __restrict__ b1,
                       const float* __restrict__ b2, const float* __restrict__ b3) {
    const int bn = blockIdx.x * 128;
    const int bm = blockIdx.y * 128;
    const int gate = bn >> 10;
    const float* W  = (gate == 0) ? W0 : (gate == 1) ? W1 : (gate == 2) ? W2 : W3;
    const float* bb = (gate == 0) ? b0 : (gate == 1) ? b1 : (gate == 2) ? b2 : b3;
    const int col0 = bn & (HID - 1);

    __shared__ uint32_t As[2][16][136];
    __shared__ uint32_t Bs[2][16][136];

    const int tid  = threadIdx.x;
    const int lane = tid & 31;
    const int warp = tid >> 5;
    const int wm   = warp >> 2;
    const int wn   = warp & 3;
    const int qg   = lane >> 2;
    const int qk   = lane & 3;

    const int ar  = tid >> 1;
    const int ac  = (tid & 1) * 8;
    const int br  = tid >> 4;
    const int bcn = tid & 15;

    float c[4][4][4];
    #pragma unroll
    for (int mt = 0; mt < 4; mt++)
        #pragma unroll
        for (int nt = 0; nt < 4; nt++)
            #pragma unroll
            for (int r = 0; r < 4; r++) c[mt][nt][r] = 0.0f;

    {
        float4 av0 = *(const float4*)&X[(size_t)(bm + ar) * DIM + ac];
        float4 av1 = *(const float4*)&X[(size_t)(bm + ar) * DIM + ac + 4];
        As[0][ac + 0][ar] = cvt_tf32(av0.x); As[0][ac + 1][ar] = cvt_tf32(av0.y);
        As[0][ac + 2][ar] = cvt_tf32(av0.z); As[0][ac + 3][ar] = cvt_tf32(av0.w);
        As[0][ac + 4][ar] = cvt_tf32(av1.x); As[0][ac + 5][ar] = cvt_tf32(av1.y);
        As[0][ac + 6][ar] = cvt_tf32(av1.z); As[0][ac + 7][ar] = cvt_tf32(av1.w);
        #pragma unroll
        for (int j = 0; j < 8; j++)
            Bs[0][br][bcn + 16 * j] =
                cvt_tf32(W[(size_t)br * HID + col0 + bcn + 16 * j]);
    }
    __syncthreads();

    int buf = 0;
    for (int kt = 0; kt < DIM / 16; kt++) {
        float4 av0, av1;
        float bvr[8];
        const int k0n = (kt + 1) * 16;
        const bool has_next = (kt + 1 < DIM / 16);
        if (has_next) {
            av0 = *(const float4*)&X[(size_t)(bm + ar) * DIM + k0n + ac];
            av1 = *(const float4*)&X[(size_t)(bm + ar) * DIM + k0n + ac + 4];
            #pragma unroll
            for (int j = 0; j < 8; j++)
                bvr[j] = W[(size_t)(k0n + br) * HID + col0 + bcn + 16 * j];
        }

        #pragma unroll
        for (int k8 = 0; k8 < 16; k8 += 8) {
            uint32_t af[4][4];
            #pragma unroll
            for (int mt = 0; mt < 4; mt++) {
                const int m = wm * 64 + mt * 16 + qg;
                af[mt][0] = As[buf][k8 + qk][m];
                af[mt][1] = As[buf][k8 + qk][m + 8];
                af[mt][2] = As[buf][k8 + 4 + qk][m];
                af[mt][3] = As[buf][k8 + 4 + qk][m + 8];
            }
            uint32_t bf[4][2];
            #pragma unroll
            for (int nt = 0; nt < 4; nt++) {
                const int n = wn * 32 + nt * 8 + qg;
                bf[nt][0] = Bs[buf][k8 + qk][n];
                bf[nt][1] = Bs[buf][k8 + 4 + qk][n];
            }
            #pragma unroll
            for (int mt = 0; mt < 4; mt++)
                #pragma unroll
                for (int nt = 0; nt < 4; nt++)
                    mma_tf32(c[mt][nt][0], c[mt][nt][1], c[mt][nt][2], c[mt][nt][3],
                             af[mt][0], af[mt][1], af[mt][2], af[mt][3],
                             bf[nt][0], bf[nt][1]);
        }

        if (has_next) {
            const int nb = buf ^ 1;
            As[nb][ac + 0][ar] = cvt_tf32(av0.x); As[nb][ac + 1][ar] = cvt_tf32(av0.y);
            As[nb][ac + 2][ar] = cvt_tf32(av0.z); As[nb][ac + 3][ar] = cvt_tf32(av0.w);
            As[nb][ac + 4][ar] = cvt_tf32(av1.x); As[nb][ac + 5][ar] = cvt_tf32(av1.y);
            As[nb][ac + 6][ar] = cvt_tf32(av1.z); As[nb][ac + 7][ar] = cvt_tf32(av1.w);
            #pragma unroll
            for (int j = 0; j < 8; j++)
                Bs[nb][br][bcn + 16 * j] = cvt_tf32(bvr[j]);
            __syncthreads();
            buf = nb;
        }
    }

    #pragma unroll
    for (int mt = 0; mt < 4; mt++) {
        #pragma unroll
        for (int nt = 0; nt < 4; nt++) {
            const int colg = wn * 32 + nt * 8 + 2 * qk;
            const float bx0 = bb[col0 + colg];
            const float bx1 = bb[col0 + colg + 1];
            const size_t row0 = (size_t)(bm + wm * 64 + mt * 16 + qg);
            float2 v0 = make_float2(c[mt][nt][0] + bx0, c[mt][nt][1] + bx1);
            float2 v1 = make_float2(c[mt][nt][2] + bx0, c[mt][nt][3] + bx1);
            *(float2*)&g_Xp[row0 * N4 + bn + colg]       = v0;
            *(float2*)&g_Xp[(row0 + 8) * N4 + bn + colg] = v1;
        }
    }
}

// ---------------- persistent recurrence kernel (fp16 m16n8k16) ---------------
// 128 blocks x 256 threads (8 warps), 1 block/SM. Block owns hidden cols
// [8*bid, 8*bid+8) x 4 gates x 64 batch rows. K split 2-way across warp
// groups. Wh resident in smem as half2 pairs; H converted to half2 on load.
// One __syncthreads per k-tile (proper double buffering).
//
// Wp[kc16=64][qk=4][gc pad 35][slot 2]  (half2 words)  : 71,680 B
// As[kg=2][buf=2][m=64][pos pad 18]     (half2 words)  : 18,432 B
// sg[kg=2][row=64][gc pad 33]           (float)        : 16,896 B
#define WP_WORDS (64 * 4 * 35 * 2)
#define AS_WORDS (2 * 2 * 64 * 18)
#define SG_WORDS (2 * 64 * 33)
#define SMEM_BYTES ((WP_WORDS + AS_WORDS + SG_WORDS) * 4)

__global__ __launch_bounds__(256)
void lstm_persistent(const float* __restrict__ H0,
                     const float* __restrict__ W0, const float* __restrict__ W1,
                     const float* __restrict__ W2, const float* __restrict__ W3,
                     float* __restrict__ out) {
    extern __shared__ unsigned char smem_raw[];
    uint32_t (*Wp)[4][35][2]  = (uint32_t (*)[4][35][2])smem_raw;
    uint32_t (*As)[2][64][18] = (uint32_t (*)[2][64][18])(smem_raw + WP_WORDS * 4);
    float    (*sg)[64][33]    = (float (*)[64][33])(smem_raw + (WP_WORDS + AS_WORDS) * 4);

    const int tid  = threadIdx.x;
    const int lane = tid & 31;
    const int warp = tid >> 5;           // 0..7
    const int colbase = blockIdx.x * 8;

    const float* Wg[4] = {W0, W1, W2, W3};

    const int kg = warp >> 2;            // K-group 0/1
    const int wq = warp & 3;
    const int wm = wq >> 1;              // rows 32*wm
    const int wn = wq & 1;               // gate-cols 16*wn
    const int qg = lane >> 2;
    const int qk = lane & 3;

    // H loader mapping (128-thread half per K-group)
    const int gtid = tid & 127;
    const int k2 = gtid & 15;            // half2 index within 32-K tile
    const int rh = gtid >> 4;            // rows rh + 8i
    // paired store position: chunk = k2>>3, within = k2&7 -> (within&3)*2 | within>>2
    const int apos = ((k2 >> 3) << 3) | ((k2 & 3) << 1) | ((k2 >> 2) & 1);

    // ---- load resident W (once) as half2 pairs ----
    {
        const int gc  = tid & 31;
        const int g   = gc >> 3;
        const int cl  = gc & 7;
        const int khb = (tid >> 5) * 64;     // each warp covers 64 half2 k-rows
        for (int j = 0; j < 64; j++) {
            const int kh = khb + j;          // 0..511
            const int k  = kh * 2;
            const float lo = Wg[g][(size_t)k * HID + colbase + cl];
            const float hi = Wg[g][(size_t)(k + 1) * HID + colbase + cl];
            const int kc16 = kh >> 3;
            const int win  = kh & 7;
            Wp[kc16][win & 3][gc][win >> 2] = pack_h2(lo, hi);
        }
    }
    __syncthreads();

    for (int t = 0; t < T_STEPS; t++) {
        const float* Hprev = (t == 0) ? H0 : out + (size_t)(t - 1) * BATCH * HID;
        const float* Xp_t  = g_Xp + (size_t)t * BATCH * N4;
        float* Hout = out + (size_t)t * BATCH * HID;

        float c[2][2][4];
        #pragma unroll
        for (int mt = 0; mt < 2; mt++)
            #pragma unroll
            for (int nt = 0; nt < 2; nt++)
                #pragma unroll
                for (int r = 0; r < 4; r++) c[mt][nt][r] = 0.0f;

        const int kbase = kg * 512;

        // preload H k-tile 0 of this half (ldcg: L2, cross-SM coherent)
        #pragma unroll
        for (int i = 0; i < 8; i++) {
            float2 h = __ldcg((const float2*)&Hprev[(size_t)(rh + 8 * i) * HID
                                                    + kbase + 2 * k2]);
            As[kg][0][rh + 8 * i][apos] = pack_h2(h.x, h.y);
        }
        __syncthreads();

        int buf = 0;
        for (int kt2 = 0; kt2 < 16; kt2++) {
            float2 hreg[8];
            const bool has_next = (kt2 + 1 < 16);
            if (has_next) {
                const int k0n = kbase + (kt2 + 1) * 32;
                #pragma unroll
                for (int i = 0; i < 8; i++)
                    hreg[i] = __ldcg((const float2*)&Hprev[(size_t)(rh + 8 * i) * HID
                                                           + k0n + 2 * k2]);
            }

            // compute on buf: 2 chunks of K=16
            #pragma unroll
            for (int ch = 0; ch < 2; ch++) {
                const int kc16 = (kg * 16 + kt2) * 2 + ch;
                uint2 a01[2], a23[2];
                #pragma unroll
                for (int mt = 0; mt < 2; mt++) {
                    const int m = 32 * wm + 16 * mt;
                    a01[mt] = *(const uint2*)&As[kg][buf][m + qg][ch * 8 + 2 * qk];
                    a23[mt] = *(const uint2*)&As[kg][buf][m + qg + 8][ch * 8 + 2 * qk];
                }
                uint2 bp[2];
                #pragma unroll
                for (int nt = 0; nt < 2; nt++) {
                    const int n = 16 * wn + 8 * nt;
                    bp[nt] = *(const uint2*)&Wp[kc16][qk][n + qg][0];
                }
                #pragma unroll
                for (int mt = 0; mt < 2; mt++)
                    #pragma unroll
                    for (int nt = 0; nt < 2; nt++)
                        mma_f16(c[mt][nt][0], c[mt][nt][1], c[mt][nt][2], c[mt][nt][3],
                                a01[mt].x, a23[mt].x, a01[mt].y, a23[mt].y,
                                bp[nt].x, bp[nt].y);
            }

            if (has_next) {
                const int nb = buf ^ 1;
                // nb was last read in tile kt2-1; all readers passed that tile's
                // closing sync. Safe to overwrite while others compute on buf.
                #pragma unroll
                for (int i = 0; i < 8; i++)
                    As[kg][nb][rh + 8 * i][apos] = pack_h2(hreg[i].x, hreg[i].y);
                __syncthreads();
                buf = nb;
            }
        }

        // stash per-K-group gate partials
        #pragma unroll
        for (int mt = 0; mt < 2; mt++) {
            #pragma unroll
            for (int nt = 0; nt < 2; nt++) {
                const int row = 32 * wm + 16 * mt + qg;
                const int cn  = 16 * wn + 8 * nt + 2 * qk;
                sg[kg][row][cn]         = c[mt][nt][0];
                sg[kg][row][cn + 1]     = c[mt][nt][1];
                sg[kg][row + 8][cn]     = c[mt][nt][2];
                sg[kg][row + 8][cn + 1] = c[mt][nt][3];
            }
        }
        __syncthreads();

        // fused LSTM cell epilogue: 64 rows x 8 cols, 2 cells/thread
        #pragma unroll
        for (int i = 0; i < 2; i++) {
            const int cell = tid + 256 * i;
            const int row  = cell >> 3;
            const int cc   = cell & 7;
            const size_t xb = (size_t)row * N4 + colbase + cc;

            float gi = sg[0][row][0  + cc] + sg[1][row][0  + cc] + Xp_t[xb + 0 * HID];
            float gf = sg[0][row][8  + cc] + sg[1][row][8  + cc] + Xp_t[xb + 1 * HID];
            float go = sg[0][row][16 + cc] + sg[1][row][16 + cc] + Xp_t[xb + 2 * HID];
            float gg = sg[0][row][24 + cc] + sg[1][row][24 + cc] + Xp_t[xb + 3 * HID];

            float I = 1.0f / (1.0f + __expf(-gi));
            float F = 1.0f / (1.0f + __expf(-gf));
            float O = 1.0f / (1.0f + __expf(-go));
            float G = tanhf(gg);

            const int idx = row * HID + colbase + cc;
            float cn2 = fmaf(F, g_C[idx], I * G);
            g_C[idx] = cn2;
            __stcg(&Hout[idx], O * tanhf(cn2));   // straight to L2
        }

        // ---- grid barrier: release(all stores) -> arrive -> acquire ----
        __threadfence();
        __syncthreads();
        if (tid == 0) {
            bar_red_release(&g_bar, 1u);
            const unsigned target = (unsigned)NBLK * (unsigned)(t + 1);
            while (bar_ld_acquire(&g_bar) < target) {}
        }
        __syncthreads();
        fence_acq_rel_gpu();
    }
}

// ---------------- tail: H_f and C_f after outputs ---------------------------
__global__ void finalize_kernel(float* __restrict__ out) {
    int i = blockIdx.x * 256 + threadIdx.x;
    if (i < BATCH * HID) {
        size_t base = (size_t)T_STEPS * BATCH * HID;
        out[base + i] = out[(size_t)(T_STEPS - 1) * BATCH * HID + i];  // H_f
        out[base + BATCH * HID + i] = g_C[i];                          // C_f
    }
}

// ---------------- launch -----------------------------------------------------
extern "C" void kernel_launch(void* const* d_in, const int* in_sizes, int n_in,
                              void* d_out, int out_size) {
    const float* X   = (const float*)d_in[0];
    const float* H0  = (const float*)d_in[1];
    const float* C0  = (const float*)d_in[2];
    const float* Wxi = (const float*)d_in[3];
    const float* Wxf = (const float*)d_in[4];
    const float* Wxo = (const float*)d_in[5];
    const float* Wxc = (const float*)d_in[6];
    const float* Whi = (const float*)d_in[7];
    const float* Whf = (const float*)d_in[8];
    const float* Who = (const float*)d_in[9];
    const float* Whc = (const float*)d_in[10];
    const float* bi  = (const float*)d_in[11];
    const float* bf  = (const float*)d_in[12];
    const float* bo  = (const float*)d_in[13];
    const float* bc  = (const float*)d_in[14];
    float* out = (float*)d_out;

    cudaFuncSetAttribute(lstm_persistent,
                         cudaFuncAttributeMaxDynamicSharedMemorySize, SMEM_BYTES);

    init_c_kernel<<<256, 256>>>(C0);
    xproj_tf32_kernel<<<dim3(32, 256), 256>>>(X, Wxi, Wxf, Wxo, Wxc,
                                              bi, bf, bo, bc);
    lstm_persistent<<<NBLK, 256, SMEM_BYTES>>>(H0, Whi, Whf, Who, Whc, out);
    finalize_kernel<<<256, 256>>>(out);
}